// round 3
// baseline (speedup 1.0000x reference)
#include <cuda_runtime.h>
#include <math.h>

#define HW    65536
#define CF    384
#define EE    256
#define GG    512
#define NCC   16

// ---- scratch layout (floats) ----
#define S_PART 0            // segsum partials [3][4][384][129] = 594432
#define S_ACNT 594432       // area counts (int) [4][129] -> 516, padded
#define S_AF   595456       // allfv  [512][768]
#define S_GL   988672       // glob   [4][384]
#define S_EM   990208       // emb    [512][256]
#define S_EP   1121280      // embp   [4][256]
#define S_CP   1122304      // comp   [4][16]
#define S_HH   1122368      // hidden [3][512][256]
#define S_RW   1515584      // rw     [3][512][64]
#define S_KF   1613888      // kf     [3][512][256]
#define S_VF   2007104      // vf     [3][512][256]
#define S_OB   2400320      // ob     [3][4][256]
#define S_OW   2403392      // obwo   [3][4][512]
#define S_P    2409536      // split-K partials (786432)
#define SCRATCH_FLOATS (2409536 + 786432)

__device__ float g_scratch[SCRATCH_FLOATS];

// ---- d_out layout (floats) ----
#define O_OCT  0
#define O_OE0  8192
#define O_OCTE 794624
#define O_GH   802816
#define O_CMP  933888
#define O_ARE  933952

// per-warp smem (floats): acc 32*129=4128, tile 32*33=1056, ids 32
#define W_ACC   0
#define W_TILE  4128
#define W_IDS   5184
#define W_SZ    5216
#define SEG_SMEM_BYTES (8 * W_SZ * 4)   // 166912

// ============================================================
// Atomic-free segment sum.
// grid (12 ch-groups, 4 batches, 3 pixel-thirds), 256 threads.
// Each warp: private [32ch][129cell] accumulator; pixel tiles of 32.
// ============================================================
__global__ void segsum2_kernel(const float* __restrict__ hd1,
                               const float* __restrict__ h1,
                               const int* __restrict__ mask,
                               float* __restrict__ partial)
{
    extern __shared__ float smem[];
    int cg = blockIdx.x, b = blockIdx.y, ps = blockIdx.z;
    int tid = threadIdx.x, lane = tid & 31, w = tid >> 5;

    // zero all per-warp accumulators (and tiles, harmless)
    for (int i = tid; i < 8 * W_SZ; i += 256) smem[i] = 0.f;
    __syncthreads();

    const float* base = (cg < 8)
        ? hd1 + (((size_t)b * 256 + cg * 32) << 16)
        : h1  + (((size_t)b * 128 + (cg - 8) * 32) << 16);
    const int* mp = mask + ((size_t)b << 16);

    float* acc  = smem + w * W_SZ + W_ACC;
    float* tile = smem + w * W_SZ + W_TILE;
    int*   ids  = (int*)(smem + w * W_SZ + W_IDS);

    // 2048 tiles of 32 pixels per batch; split into thirds
    int tb = ps * 683;
    int te = (ps < 2) ? tb + 683 : 2048;

    for (int t = tb + w; t < te; t += 8) {
        int p0 = t * 32;
        ids[lane] = mp[p0 + lane];
        // stage 32 channels x 32 pixels, transposed
        const float* cp = base + p0 + lane;
#pragma unroll
        for (int c = 0; c < 32; c++)
            tile[c * 33 + lane] = cp[(size_t)c << 16];
        __syncwarp();
#pragma unroll
        for (int p = 0; p < 32; p++) {
            int idp = ids[p];                      // uniform broadcast
            acc[lane * 129 + idp] += tile[lane * 33 + p];
        }
        __syncwarp();
    }
    __syncthreads();

    // reduce 8 warps -> partial[ps][b][cg*32 .. +32][129]
    float* outp = partial + (((size_t)(ps * 4 + b) * 384 + cg * 32) * 129);
    for (int i = tid; i < 32 * 129; i += 256) {
        float s = 0.f;
#pragma unroll
        for (int ww = 0; ww < 8; ww++) s += smem[ww * W_SZ + i];
        outp[i] = s;
    }
}

// ============================================================
__global__ void zero_acnt(int* __restrict__ cnt)
{
    int i = threadIdx.x;
    if (i < 516) cnt[i] = 0;
}

__global__ void hist_kernel(const int* __restrict__ mask, int* __restrict__ cnt)
{
    int b = blockIdx.x, ch = blockIdx.y, tid = threadIdx.x;
    __shared__ int h[129];
    if (tid < 129) h[tid] = 0;
    __syncthreads();
    const int* mp = mask + ((size_t)b << 16) + ch * 4096;
    for (int i = tid; i < 4096; i += 256)
        atomicAdd(&h[mp[i]], 1);
    __syncthreads();
    if (tid < 129 && h[tid]) atomicAdd(&cnt[b * 129 + tid], h[tid]);
}

// ============================================================
__global__ void glob_kernel(const float* __restrict__ partial, float* __restrict__ glob)
{
    int b = blockIdx.x, c = threadIdx.x;   // 384 threads
    float s = 0.f;
    for (int ps = 0; ps < 3; ps++) {
        const float* p = partial + ((size_t)(ps * 4 + b) * 384 + c) * 129;
#pragma unroll 4
        for (int i = 0; i < 129; i++) s += p[i];
    }
    glob[b * CF + c] = s * (1.f / HW);
}

// ============================================================
__global__ void finalize2(const float* __restrict__ partial,
                          const int* __restrict__ acnt,
                          const float* __restrict__ glob,
                          float* __restrict__ allfv, float* __restrict__ out_area)
{
    int n = blockIdx.x, tid = threadIdx.x;
    int b = n >> 7, cell = n & 127;
    int a = acnt[b * 129 + cell + 1];
    if (tid == 0) out_area[n] = (float)a;
    float inva = 1.f / fmaxf((float)a, 1.f);
    for (int j = tid; j < 768; j += 256) {
        float v;
        if (j < CF) {
            v = partial[((size_t)(0 * 4 + b) * 384 + j) * 129 + cell + 1]
              + partial[((size_t)(1 * 4 + b) * 384 + j) * 129 + cell + 1]
              + partial[((size_t)(2 * 4 + b) * 384 + j) * 129 + cell + 1];
            v *= inva;
        } else {
            v = glob[b * CF + (j - CF)];
        }
        allfv[(size_t)n * 768 + j] = v;
    }
}

// ============================================================
// GEMM: 64x64 tile, BK=16, 4x4 microtile, 256 threads. (unchanged)
// ============================================================
__global__ void gemm64(const float* __restrict__ A, int lda, long long sAz,
                       const float* __restrict__ B, int ldb, long long sBz,
                       float* __restrict__ C, int ldc, long long sCz,
                       int M, int N, int K, int KS, int relu)
{
    int KC = K / KS;
    int br = blockIdx.z / KS, kc = blockIdx.z - br * KS;
    A += (size_t)br * sAz + (size_t)kc * KC;
    B += (size_t)br * sBz + (size_t)kc * KC * ldb;
    if (KS == 1) C += (size_t)br * sCz;
    else         C += (size_t)blockIdx.z * ((size_t)M * ldc);

    __shared__ float As[16][64];
    __shared__ float Bs[16][64];
    int tid = threadIdx.x;
    int tx = tid & 15, ty = tid >> 4;
    int row0 = blockIdx.y * 64, col0 = blockIdx.x * 64;

    int arow = tid >> 2, ak4 = (tid & 3) * 4;
    int brow = tid >> 4, bc4 = (tid & 15) * 4;

    const float* Ap = A + (size_t)(row0 + arow) * lda + ak4;
    const float* Bp = B + (size_t)brow * ldb + col0 + bc4;

    float acc[4][4] = {};
    for (int k0 = 0; k0 < KC; k0 += 16) {
        float4 av = *(const float4*)(Ap + k0);
        float4 bv = *(const float4*)(Bp + (size_t)k0 * ldb);
        As[ak4 + 0][arow] = av.x;
        As[ak4 + 1][arow] = av.y;
        As[ak4 + 2][arow] = av.z;
        As[ak4 + 3][arow] = av.w;
        *(float4*)&Bs[brow][bc4] = bv;
        __syncthreads();
#pragma unroll
        for (int k = 0; k < 16; k++) {
            float4 a = *(const float4*)&As[k][ty * 4];
            float4 b = *(const float4*)&Bs[k][tx * 4];
            acc[0][0] += a.x * b.x; acc[0][1] += a.x * b.y; acc[0][2] += a.x * b.z; acc[0][3] += a.x * b.w;
            acc[1][0] += a.y * b.x; acc[1][1] += a.y * b.y; acc[1][2] += a.y * b.z; acc[1][3] += a.y * b.w;
            acc[2][0] += a.z * b.x; acc[2][1] += a.z * b.y; acc[2][2] += a.z * b.z; acc[2][3] += a.z * b.w;
            acc[3][0] += a.w * b.x; acc[3][1] += a.w * b.y; acc[3][2] += a.w * b.z; acc[3][3] += a.w * b.w;
        }
        __syncthreads();
    }
#pragma unroll
    for (int i = 0; i < 4; i++) {
        float4 v = make_float4(acc[i][0], acc[i][1], acc[i][2], acc[i][3]);
        if (relu && KS == 1) {
            v.x = fmaxf(v.x, 0.f); v.y = fmaxf(v.y, 0.f);
            v.z = fmaxf(v.z, 0.f); v.w = fmaxf(v.w, 0.f);
        }
        *(float4*)&C[(size_t)(row0 + ty * 4 + i) * ldc + col0 + tx * 4] = v;
    }
}

__global__ void reducek_kernel(const float* __restrict__ P, float* __restrict__ C,
                               long long sCz, long long slice, int KS, int relu)
{
    int brz = blockIdx.y;
    long long idx = (long long)blockIdx.x * 256 + threadIdx.x;
    const float* p = P + (size_t)brz * KS * slice + idx;
    float s = 0.f;
    for (int j = 0; j < KS; j++) s += p[(size_t)j * slice];
    if (relu) s = fmaxf(s, 0.f);
    C[(size_t)brz * sCz + idx] = s;
}

// ============================================================
__global__ void gemmN16(const float* __restrict__ A, const float* __restrict__ B,
                        float* __restrict__ C, int K, int relu)
{
    extern __shared__ float As[];
    int tid = threadIdx.x;
    int row0 = blockIdx.x * 32;
    for (int i = tid; i < 32 * K; i += 256)
        As[i] = A[(size_t)row0 * K + i];
    __syncthreads();
    int r = tid >> 3, cg = tid & 7;
    int c0 = cg * 2;
    float s0 = 0.f, s1 = 0.f;
    const float* ar = As + r * K;
#pragma unroll 4
    for (int k = 0; k < K; k++) {
        float a = ar[k];
        s0 += a * B[k * 16 + c0];
        s1 += a * B[k * 16 + c0 + 1];
    }
    if (relu) { s0 = fmaxf(s0, 0.f); s1 = fmaxf(s1, 0.f); }
    C[(size_t)(row0 + r) * 16 + c0]     = s0;
    C[(size_t)(row0 + r) * 16 + c0 + 1] = s1;
}

// ============================================================
__global__ void embp_kernel(const float* __restrict__ emb, float* __restrict__ embp)
{
    int b = blockIdx.x, e = threadIdx.x;
    float s = 0.f;
    for (int i = 0; i < 128; i++)
        s += emb[(size_t)(b * 128 + i) * EE + e];
    embp[b * EE + e] = s * (1.f / 128.f);
}

// ============================================================
__global__ void comp_fused(const float* __restrict__ embp,
                           const float* __restrict__ w1, const float* __restrict__ w2,
                           float* __restrict__ comp, float* __restrict__ comp_out)
{
    int b = blockIdx.x, tid = threadIdx.x;
    __shared__ float ep[EE];
    __shared__ float t1[EE];
    __shared__ float t2[NCC];
    ep[tid] = embp[b * EE + tid];
    __syncthreads();
    float s = 0.f;
    for (int c = 0; c < EE; c++)
        s += ep[c] * w1[(size_t)c * EE + tid];
    t1[tid] = fmaxf(s, 0.f);
    __syncthreads();
    if (tid < NCC) {
        float s2 = 0.f;
        for (int j = 0; j < EE; j++)
            s2 += t1[j] * w2[(size_t)j * NCC + tid];
        t2[tid] = s2;
    }
    __syncthreads();
    if (tid == 0) {
        float m = t2[0];
        for (int o = 1; o < NCC; o++) m = fmaxf(m, t2[o]);
        float tot = 0.f;
        float e[NCC];
        for (int o = 0; o < NCC; o++) { e[o] = expf(t2[o] - m); tot += e[o]; }
        float inv = 1.f / tot;
        for (int o = 0; o < NCC; o++) {
            comp[b * NCC + o] = e[o] * inv;
            comp_out[b * NCC + o] = e[o] * inv;
        }
    }
}

// ============================================================
__global__ void softmax64_kernel(float* __restrict__ x)
{
    int r = blockIdx.x, tid = threadIdx.x;
    float* row = x + (size_t)r * 64;
    float v = row[tid];
    __shared__ float sm[4];
    int lane = tid & 31, warp = tid >> 5;
    float m = v;
    for (int off = 16; off; off >>= 1) m = fmaxf(m, __shfl_xor_sync(0xffffffff, m, off));
    if (lane == 0) sm[warp] = m;
    __syncthreads();
    m = fmaxf(sm[0], sm[1]);
    float e = expf(v - m);
    float s = e;
    for (int off = 16; off; off >>= 1) s += __shfl_xor_sync(0xffffffff, s, off);
    if (lane == 0) sm[2 + warp] = s;
    __syncthreads();
    s = sm[2] + sm[3];
    row[tid] = e / s;
}

// ============================================================
__global__ void attn_kernel(const float* __restrict__ comp,
                            const float* __restrict__ ca_wq,
                            const float* __restrict__ kf,
                            const float* __restrict__ vf,
                            float* __restrict__ ob)
{
    int b = blockIdx.x, h = blockIdx.y, br = blockIdx.z;
    int tid = threadIdx.x, lane = tid & 31, warp = tid >> 5;
    const float* wq  = ca_wq + (size_t)br * 16 * EE;
    const float* kfp = kf + (size_t)br * 512 * EE;
    const float* vfp = vf + (size_t)br * 512 * EE;

    __shared__ float q[32];
    __shared__ float sc[512];
    __shared__ float r1[256];
    __shared__ float part[8][32];

    if (tid < 32) {
        float s = 0.f;
        for (int c = 0; c < NCC; c++)
            s += comp[b * NCC + c] * wq[(size_t)c * EE + h * 32 + tid];
        q[tid] = s * 0.17677669529663687f;
    }
    __syncthreads();

    for (int kk = 0; kk < 64; kk++) {
        int kn = warp * 64 + kk;
        float p = q[lane] * kfp[(size_t)kn * EE + h * 32 + lane];
        for (int off = 16; off; off >>= 1) p += __shfl_down_sync(0xffffffff, p, off);
        if (lane == 0) sc[kn] = p;
    }
    __syncthreads();

    float m = fmaxf(sc[tid], sc[tid + 256]);
    r1[tid] = m; __syncthreads();
    for (int s = 128; s > 0; s >>= 1) { if (tid < s) r1[tid] = fmaxf(r1[tid], r1[tid + s]); __syncthreads(); }
    float maxv = r1[0]; __syncthreads();
    float e0 = expf(sc[tid] - maxv), e1 = expf(sc[tid + 256] - maxv);
    sc[tid] = e0; sc[tid + 256] = e1;
    r1[tid] = e0 + e1; __syncthreads();
    for (int s = 128; s > 0; s >>= 1) { if (tid < s) r1[tid] += r1[tid + s]; __syncthreads(); }
    float invs = 1.f / r1[0];

    float a = 0.f;
    for (int kn = warp; kn < 512; kn += 8)
        a += sc[kn] * vfp[(size_t)kn * EE + h * 32 + lane];
    part[warp][lane] = a;
    __syncthreads();
    if (tid < 32) {
        float s = 0.f;
        for (int w = 0; w < 8; w++) s += part[w][tid];
        ob[((size_t)br * 4 + b) * EE + h * 32 + tid] = s * invs;
    }
}

// ============================================================
__global__ void obwo_kernel(const float* __restrict__ ob, const float* __restrict__ ca_wo,
                            float* __restrict__ obwo)
{
    int b = blockIdx.x, br = blockIdx.z, tid = threadIdx.x;
    const float* wo = ca_wo + (size_t)br * EE * GG;
    __shared__ float obs[EE];
    if (tid < EE) obs[tid] = ob[((size_t)br * 4 + b) * EE + tid];
    __syncthreads();
    float s = 0.f;
    for (int c = 0; c < EE; c++)
        s += obs[c] * wo[(size_t)c * GG + tid];
    obwo[((size_t)br * 4 + b) * GG + tid] = s;
}

// ============================================================
__global__ void addrelu_kernel(float* __restrict__ oe_base, const float* __restrict__ obwo)
{
    int n = blockIdx.x, br = blockIdx.z, g = threadIdx.x;
    int b = n >> 7;
    float* oe = oe_base + (size_t)br * 262144;
    float v = oe[(size_t)n * GG + g] + obwo[((size_t)br * 4 + b) * GG + g];
    oe[(size_t)n * GG + g] = fmaxf(v, 0.f);
}

// ============================================================
static inline void launch_gemm(const float* A, int lda, long long sAz,
                               const float* B, int ldb, long long sBz,
                               float* C, int ldc, long long sCz,
                               int M, int N, int K, int relu, int nz, int KS,
                               float* partial)
{
    dim3 grid(N / 64, M / 64, nz * KS);
    if (KS == 1) {
        gemm64<<<grid, 256>>>(A, lda, sAz, B, ldb, sBz, C, ldc, sCz, M, N, K, 1, relu);
    } else {
        gemm64<<<grid, 256>>>(A, lda, sAz, B, ldb, sBz, partial, ldc, 0, M, N, K, KS, 0);
        long long slice = (long long)M * ldc;
        reducek_kernel<<<dim3((unsigned)(slice / 256), nz), 256>>>(partial, C, sCz, slice, KS, relu);
    }
}

extern "C" void kernel_launch(void* const* d_in, const int* in_sizes, int n_in,
                              void* d_out, int out_size)
{
    (void)in_sizes; (void)n_in; (void)out_size;
    const float* hd1      = (const float*)d_in[0];
    const float* h1       = (const float*)d_in[1];
    const float* ref_orig = (const float*)d_in[2];
    const float* embed_w  = (const float*)d_in[3];
    const float* comp_w1  = (const float*)d_in[4];
    const float* comp_w2  = (const float*)d_in[5];
    const float* hist_w1  = (const float*)d_in[6];
    const float* hist_w2  = (const float*)d_in[7];
    const float* genes_w1 = (const float*)d_in[8];
    const float* genes_w2 = (const float*)d_in[9];
    const float* wref_w1  = (const float*)d_in[10];
    const float* wref_w2  = (const float*)d_in[11];
    const float* ca_wq    = (const float*)d_in[12];
    const float* ca_wk    = (const float*)d_in[13];
    const float* ca_wv    = (const float*)d_in[14];
    const float* ca_wo    = (const float*)d_in[15];
    const int*   mask     = (const int*)d_in[16];
    float* out = (float*)d_out;

    float* sc = nullptr;
    cudaGetSymbolAddress((void**)&sc, g_scratch);
    float* P = sc + S_P;
    int* acnt = (int*)(sc + S_ACNT);

    static int seg_attr_done = 0;
    if (!seg_attr_done) {
        cudaFuncSetAttribute(segsum2_kernel,
                             cudaFuncAttributeMaxDynamicSharedMemorySize, SEG_SMEM_BYTES);
        seg_attr_done = 1;
    }

    // 1. area histogram (int, deterministic)
    zero_acnt<<<1, 516>>>(acnt);
    hist_kernel<<<dim3(4, 16), 256>>>(mask, acnt);
    // 2. atomic-free segment sums
    segsum2_kernel<<<dim3(12, 4, 3), 256, SEG_SMEM_BYTES>>>(hd1, h1, mask, sc + S_PART);
    // 3. glob from partial sums
    glob_kernel<<<4, 384>>>(sc + S_PART, sc + S_GL);
    // 4. all_fv
    finalize2<<<512, 256>>>(sc + S_PART, acnt, sc + S_GL, sc + S_AF, out + O_ARE);
    // 5. emb = all_fv @ embed_w  [512,256], K=768, split-K 4
    launch_gemm(sc + S_AF, 768, 0, embed_w, EE, 0, sc + S_EM, EE, 0,
                512, EE, 768, 0, 1, 4, P);
    // 6. emb_patches
    embp_kernel<<<4, 256>>>(sc + S_EM, sc + S_EP);
    // 7. comp
    comp_fused<<<4, 256>>>(sc + S_EP, comp_w1, comp_w2, sc + S_CP, out + O_CMP);
    // 8. hist hidden
    launch_gemm(sc + S_EM, EE, 0, hist_w1, EE, 0, sc + S_HH, EE, 0,
                512, EE, EE, 1, 1, 4, P);
    // 9. out_cell_type
    gemmN16<<<16, 256, 32 * EE * sizeof(float)>>>(sc + S_HH, hist_w2, out + O_OCT, EE, 0);
    // 10. branch hidden
    launch_gemm(sc + S_EM, EE, 0, wref_w1, EE, (long long)EE * EE,
                sc + S_HH, EE, (long long)512 * EE, 512, EE, EE, 1, 3, 2, P);
    // 11. rw logits
    launch_gemm(sc + S_HH, EE, (long long)512 * EE, wref_w2, 64, (long long)EE * 64,
                sc + S_RW, 64, (long long)512 * 64, 512, 64, EE, 0, 3, 4, P);
    // 12. softmax rows
    softmax64_kernel<<<3 * 512, 64>>>(sc + S_RW);
    // 13. refw = rw @ ref_orig
    launch_gemm(sc + S_RW, 64, (long long)512 * 64, ref_orig, GG, 0,
                out + O_OE0, GG, 262144LL, 512, GG, 64, 0, 3, 1, P);
    // 14-15. kf/vf
    launch_gemm(out + O_OE0, GG, 262144LL, ca_wk, EE, (long long)GG * EE,
                sc + S_KF, EE, (long long)512 * EE, 512, EE, GG, 0, 3, 2, P);
    launch_gemm(out + O_OE0, GG, 262144LL, ca_wv, EE, (long long)GG * EE,
                sc + S_VF, EE, (long long)512 * EE, 512, EE, GG, 0, 3, 2, P);
    // 16. attention
    attn_kernel<<<dim3(4, 8, 3), 256>>>(sc + S_CP, ca_wq, sc + S_KF, sc + S_VF, sc + S_OB);
    // 17. obwo
    obwo_kernel<<<dim3(4, 1, 3), 512>>>(sc + S_OB, ca_wo, sc + S_OW);
    // 18. out_exprs = relu(refw + tile(obwo))
    addrelu_kernel<<<dim3(512, 1, 3), 512>>>(out + O_OE0, sc + S_OW);
    // 19. genes_h
    launch_gemm(out + O_OE0, GG, 0, genes_w1, EE, 0, out + O_GH, EE, 0,
                512, EE, GG, 1, 1, 4, P);
    // 20. out_cell_type_expr
    gemmN16<<<16, 256, 32 * EE * sizeof(float)>>>(out + O_GH, genes_w2, out + O_OCTE, EE, 0);
}

// round 4
// speedup vs baseline: 1.0922x; 1.0922x over previous
#include <cuda_runtime.h>
#include <math.h>

#define HW    65536
#define CF    384
#define EE    256
#define GG    512
#define NCC   16

// ---- scratch layout (floats) ----
#define S_PART 0            // segsum partials [3ps][4b][129cell][384ch] = 594432
#define S_GLP  594432       // glob partials [3ps][4b][384] = 4608
#define S_ACNT 599040       // area counts (int) [4][129], padded to 1024
#define S_AF   600064       // allfv  [512][768]
#define S_EM   993280       // emb    [512][256]
#define S_EP   1124352      // embp   [4][256]
#define S_CP   1125376      // comp   [4][16] (pad 64)
#define S_HH   1125440      // hidden [3][512][256]
#define S_RW   1518656      // rw     [3][512][64]
#define S_KF   1616960      // kf     [3][512][256]
#define S_VF   2010176      // vf     [3][512][256]
#define S_OB   2403392      // ob     [3][4][256]
#define S_OW   2406464      // obwo   [3][4][512] (pad)
#define S_P    2412608      // split-K partials (786432)
#define SCRATCH_FLOATS (2412608 + 786432)

__device__ float g_scratch[SCRATCH_FLOATS];

// ---- d_out layout (floats) ----
#define O_OCT  0
#define O_OE0  8192
#define O_OCTE 794624
#define O_GH   802816
#define O_CMP  933888
#define O_ARE  933952

// per-warp smem (floats): acc 32*129=4128, tile 32*33=1056, ids/tot 32
#define W_TILE  4128
#define W_IDS   5184
#define W_SZ    5216
#define SEG_SMEM_BYTES (8 * W_SZ * 4)   // 166912

// ============================================================
// Atomic-free segment sum, 4-way ILP accumulate chains.
// grid (12 ch-groups, 4 batches, 3 pixel-thirds), 256 threads.
// Each warp: private [32ch][129cell] smem accumulator (lane-private rows).
// ids are warp-uniform -> duplicate merge via uniform predicates.
// ============================================================
__global__ void segsum2_kernel(const float* __restrict__ hd1,
                               const float* __restrict__ h1,
                               const int* __restrict__ mask,
                               float* __restrict__ partial,
                               float* __restrict__ globpart)
{
    extern __shared__ float smem[];
    int cg = blockIdx.x, b = blockIdx.y, ps = blockIdx.z;
    int tid = threadIdx.x, lane = tid & 31, w = tid >> 5;

    for (int i = tid; i < 8 * W_SZ; i += 256) smem[i] = 0.f;
    __syncthreads();

    const float* base = (cg < 8)
        ? hd1 + (((size_t)b * 256 + cg * 32) << 16)
        : h1  + (((size_t)b * 128 + (cg - 8) * 32) << 16);
    const int* mp = mask + ((size_t)b << 16);

    float* acc  = smem + w * W_SZ;           // [lane][129]
    float* tile = smem + w * W_SZ + W_TILE;  // [ch][33]
    int*   ids  = (int*)(smem + w * W_SZ + W_IDS);
    int L = lane * 129;
    int T = lane * 33;
    float tot = 0.f;                          // per-channel(=lane) plain sum

    int tb = ps * 683;
    int te = (ps < 2) ? tb + 683 : 2048;

    for (int t = tb + w; t < te; t += 8) {
        int p0 = t * 32;
        ids[lane] = mp[p0 + lane];
        const float* cp = base + p0 + lane;
#pragma unroll
        for (int c = 0; c < 32; c++)
            tile[c * 33 + lane] = cp[(size_t)c << 16];
        __syncwarp();
#pragma unroll
        for (int p = 0; p < 32; p += 4) {
            int i0 = ids[p], i1 = ids[p + 1], i2 = ids[p + 2], i3 = ids[p + 3];
            float t0 = tile[T + p],     t1 = tile[T + p + 1];
            float t2 = tile[T + p + 2], t3 = tile[T + p + 3];
            tot += (t0 + t1) + (t2 + t3);
            bool u1 = (i1 != i0);
            bool u2 = (i2 != i0) && (i2 != i1);
            bool u3 = (i3 != i0) && (i3 != i1) && (i3 != i2);
            if (!u3) { if (i3 == i0) t0 += t3; else if (i3 == i1) t1 += t3; else t2 += t3; }
            if (!u2) { if (i2 == i0) t0 += t2; else t1 += t2; }
            if (!u1) t0 += t1;
            float a0 = acc[L + i0] + t0;
            float a1 = u1 ? acc[L + i1] + t1 : 0.f;
            float a2 = u2 ? acc[L + i2] + t2 : 0.f;
            float a3 = u3 ? acc[L + i3] + t3 : 0.f;
            acc[L + i0] = a0;
            if (u1) acc[L + i1] = a1;
            if (u2) acc[L + i2] = a2;
            if (u3) acc[L + i3] = a3;
        }
        __syncwarp();
    }

    // stash per-warp channel totals (warp-private region)
    __syncwarp();
    ((float*)ids)[lane] = tot;
    __syncthreads();

    // globpart[ps][b][384]
    if (tid < 32) {
        float s = 0.f;
#pragma unroll
        for (int ww = 0; ww < 8; ww++) s += smem[ww * W_SZ + W_IDS + tid];
        globpart[(size_t)(ps * 4 + b) * 384 + cg * 32 + tid] = s;
    }

    // partial[ps][b][cell][ch] (cell-major, coalesced 128B writes)
    float* outp = partial + ((size_t)(ps * 4 + b) * 129 * 384) + cg * 32;
    for (int i = tid; i < 129 * 32; i += 256) {
        int cell = i >> 5, ch = i & 31;
        float s = 0.f;
#pragma unroll
        for (int ww = 0; ww < 8; ww++) s += smem[ww * W_SZ + ch * 129 + cell];
        outp[(size_t)cell * 384 + ch] = s;
    }
}

// ============================================================
__global__ void zero_acnt(int* __restrict__ cnt)
{
    int i = threadIdx.x;
    if (i < 516) cnt[i] = 0;
}

__global__ void hist_kernel(const int* __restrict__ mask, int* __restrict__ cnt)
{
    int b = blockIdx.x, ch = blockIdx.y, tid = threadIdx.x;
    __shared__ int h[129];
    if (tid < 129) h[tid] = 0;
    __syncthreads();
    const int* mp = mask + ((size_t)b << 16) + ch * 4096;
    for (int i = tid; i < 4096; i += 256)
        atomicAdd(&h[mp[i]], 1);
    __syncthreads();
    if (tid < 129 && h[tid]) atomicAdd(&cnt[b * 129 + tid], h[tid]);
}

// ============================================================
// allfv from cell-major partials; glob summed inline (deterministic).
// ============================================================
__global__ void finalize2(const float* __restrict__ partial,
                          const int* __restrict__ acnt,
                          const float* __restrict__ globpart,
                          float* __restrict__ allfv, float* __restrict__ out_area)
{
    int n = blockIdx.x, tid = threadIdx.x;
    int b = n >> 7, cell = n & 127;
    int a = acnt[b * 129 + cell + 1];
    if (tid == 0) out_area[n] = (float)a;
    float inva = 1.f / fmaxf((float)a, 1.f);
    const size_t PS = (size_t)4 * 129 * 384;
    size_t rp0 = (size_t)b * 129 * 384 + (size_t)(cell + 1) * 384;
    for (int j = tid; j < 768; j += 256) {
        float v;
        if (j < 384) {
            v = (partial[rp0 + j] + partial[rp0 + PS + j] + partial[rp0 + 2 * PS + j]) * inva;
        } else {
            int c = j - 384;
            v = (globpart[(size_t)b * 384 + c] + globpart[(size_t)(4 + b) * 384 + c]
               + globpart[(size_t)(8 + b) * 384 + c]) * (1.f / 65536.f);
        }
        allfv[(size_t)n * 768 + j] = v;
    }
}

// ============================================================
// GEMM: 64x64 tile, BK=16, 4x4 microtile, 256 threads. (unchanged)
// ============================================================
__global__ void gemm64(const float* __restrict__ A, int lda, long long sAz,
                       const float* __restrict__ B, int ldb, long long sBz,
                       float* __restrict__ C, int ldc, long long sCz,
                       int M, int N, int K, int KS, int relu)
{
    int KC = K / KS;
    int br = blockIdx.z / KS, kc = blockIdx.z - br * KS;
    A += (size_t)br * sAz + (size_t)kc * KC;
    B += (size_t)br * sBz + (size_t)kc * KC * ldb;
    if (KS == 1) C += (size_t)br * sCz;
    else         C += (size_t)blockIdx.z * ((size_t)M * ldc);

    __shared__ float As[16][64];
    __shared__ float Bs[16][64];
    int tid = threadIdx.x;
    int tx = tid & 15, ty = tid >> 4;
    int row0 = blockIdx.y * 64, col0 = blockIdx.x * 64;

    int arow = tid >> 2, ak4 = (tid & 3) * 4;
    int brow = tid >> 4, bc4 = (tid & 15) * 4;

    const float* Ap = A + (size_t)(row0 + arow) * lda + ak4;
    const float* Bp = B + (size_t)brow * ldb + col0 + bc4;

    float acc[4][4] = {};
    for (int k0 = 0; k0 < KC; k0 += 16) {
        float4 av = *(const float4*)(Ap + k0);
        float4 bv = *(const float4*)(Bp + (size_t)k0 * ldb);
        As[ak4 + 0][arow] = av.x;
        As[ak4 + 1][arow] = av.y;
        As[ak4 + 2][arow] = av.z;
        As[ak4 + 3][arow] = av.w;
        *(float4*)&Bs[brow][bc4] = bv;
        __syncthreads();
#pragma unroll
        for (int k = 0; k < 16; k++) {
            float4 a = *(const float4*)&As[k][ty * 4];
            float4 b = *(const float4*)&Bs[k][tx * 4];
            acc[0][0] += a.x * b.x; acc[0][1] += a.x * b.y; acc[0][2] += a.x * b.z; acc[0][3] += a.x * b.w;
            acc[1][0] += a.y * b.x; acc[1][1] += a.y * b.y; acc[1][2] += a.y * b.z; acc[1][3] += a.y * b.w;
            acc[2][0] += a.z * b.x; acc[2][1] += a.z * b.y; acc[2][2] += a.z * b.z; acc[2][3] += a.z * b.w;
            acc[3][0] += a.w * b.x; acc[3][1] += a.w * b.y; acc[3][2] += a.w * b.z; acc[3][3] += a.w * b.w;
        }
        __syncthreads();
    }
#pragma unroll
    for (int i = 0; i < 4; i++) {
        float4 v = make_float4(acc[i][0], acc[i][1], acc[i][2], acc[i][3]);
        if (relu && KS == 1) {
            v.x = fmaxf(v.x, 0.f); v.y = fmaxf(v.y, 0.f);
            v.z = fmaxf(v.z, 0.f); v.w = fmaxf(v.w, 0.f);
        }
        *(float4*)&C[(size_t)(row0 + ty * 4 + i) * ldc + col0 + tx * 4] = v;
    }
}

__global__ void reducek_kernel(const float* __restrict__ P, float* __restrict__ C,
                               long long sCz, long long slice, int KS, int relu)
{
    int brz = blockIdx.y;
    long long idx = (long long)blockIdx.x * 256 + threadIdx.x;
    const float* p = P + (size_t)brz * KS * slice + idx;
    float s = 0.f;
    for (int j = 0; j < KS; j++) s += p[(size_t)j * slice];
    if (relu) s = fmaxf(s, 0.f);
    C[(size_t)brz * sCz + idx] = s;
}

// ============================================================
__global__ void gemmN16(const float* __restrict__ A, const float* __restrict__ B,
                        float* __restrict__ C, int K, int relu)
{
    extern __shared__ float As[];
    int tid = threadIdx.x;
    int row0 = blockIdx.x * 32;
    for (int i = tid; i < 32 * K; i += 256)
        As[i] = A[(size_t)row0 * K + i];
    __syncthreads();
    int r = tid >> 3, cg = tid & 7;
    int c0 = cg * 2;
    float s0 = 0.f, s1 = 0.f;
    const float* ar = As + r * K;
#pragma unroll 4
    for (int k = 0; k < K; k++) {
        float a = ar[k];
        s0 += a * B[k * 16 + c0];
        s1 += a * B[k * 16 + c0 + 1];
    }
    if (relu) { s0 = fmaxf(s0, 0.f); s1 = fmaxf(s1, 0.f); }
    C[(size_t)(row0 + r) * 16 + c0]     = s0;
    C[(size_t)(row0 + r) * 16 + c0 + 1] = s1;
}

// ============================================================
__global__ void embp_kernel(const float* __restrict__ emb, float* __restrict__ embp)
{
    int b = blockIdx.x, e = threadIdx.x;
    float s = 0.f;
    for (int i = 0; i < 128; i++)
        s += emb[(size_t)(b * 128 + i) * EE + e];
    embp[b * EE + e] = s * (1.f / 128.f);
}

// ============================================================
__global__ void comp_fused(const float* __restrict__ embp,
                           const float* __restrict__ w1, const float* __restrict__ w2,
                           float* __restrict__ comp, float* __restrict__ comp_out)
{
    int b = blockIdx.x, tid = threadIdx.x;
    __shared__ float ep[EE];
    __shared__ float t1[EE];
    __shared__ float t2[NCC];
    ep[tid] = embp[b * EE + tid];
    __syncthreads();
    float s = 0.f;
    for (int c = 0; c < EE; c++)
        s += ep[c] * w1[(size_t)c * EE + tid];
    t1[tid] = fmaxf(s, 0.f);
    __syncthreads();
    if (tid < NCC) {
        float s2 = 0.f;
        for (int j = 0; j < EE; j++)
            s2 += t1[j] * w2[(size_t)j * NCC + tid];
        t2[tid] = s2;
    }
    __syncthreads();
    if (tid == 0) {
        float m = t2[0];
        for (int o = 1; o < NCC; o++) m = fmaxf(m, t2[o]);
        float tot = 0.f;
        float e[NCC];
        for (int o = 0; o < NCC; o++) { e[o] = expf(t2[o] - m); tot += e[o]; }
        float inv = 1.f / tot;
        for (int o = 0; o < NCC; o++) {
            comp[b * NCC + o] = e[o] * inv;
            comp_out[b * NCC + o] = e[o] * inv;
        }
    }
}

// ============================================================
__global__ void softmax64_kernel(float* __restrict__ x)
{
    int r = blockIdx.x, tid = threadIdx.x;
    float* row = x + (size_t)r * 64;
    float v = row[tid];
    __shared__ float sm[4];
    int lane = tid & 31, warp = tid >> 5;
    float m = v;
    for (int off = 16; off; off >>= 1) m = fmaxf(m, __shfl_xor_sync(0xffffffff, m, off));
    if (lane == 0) sm[warp] = m;
    __syncthreads();
    m = fmaxf(sm[0], sm[1]);
    float e = expf(v - m);
    float s = e;
    for (int off = 16; off; off >>= 1) s += __shfl_xor_sync(0xffffffff, s, off);
    if (lane == 0) sm[2 + warp] = s;
    __syncthreads();
    s = sm[2] + sm[3];
    row[tid] = e / s;
}

// ============================================================
__global__ void attn_kernel(const float* __restrict__ comp,
                            const float* __restrict__ ca_wq,
                            const float* __restrict__ kf,
                            const float* __restrict__ vf,
                            float* __restrict__ ob)
{
    int b = blockIdx.x, h = blockIdx.y, br = blockIdx.z;
    int tid = threadIdx.x, lane = tid & 31, warp = tid >> 5;
    const float* wq  = ca_wq + (size_t)br * 16 * EE;
    const float* kfp = kf + (size_t)br * 512 * EE;
    const float* vfp = vf + (size_t)br * 512 * EE;

    __shared__ float q[32];
    __shared__ float sc[512];
    __shared__ float r1[256];
    __shared__ float part[8][32];

    if (tid < 32) {
        float s = 0.f;
        for (int c = 0; c < NCC; c++)
            s += comp[b * NCC + c] * wq[(size_t)c * EE + h * 32 + tid];
        q[tid] = s * 0.17677669529663687f;
    }
    __syncthreads();

    for (int kk = 0; kk < 64; kk++) {
        int kn = warp * 64 + kk;
        float p = q[lane] * kfp[(size_t)kn * EE + h * 32 + lane];
        for (int off = 16; off; off >>= 1) p += __shfl_down_sync(0xffffffff, p, off);
        if (lane == 0) sc[kn] = p;
    }
    __syncthreads();

    float m = fmaxf(sc[tid], sc[tid + 256]);
    r1[tid] = m; __syncthreads();
    for (int s = 128; s > 0; s >>= 1) { if (tid < s) r1[tid] = fmaxf(r1[tid], r1[tid + s]); __syncthreads(); }
    float maxv = r1[0]; __syncthreads();
    float e0 = expf(sc[tid] - maxv), e1 = expf(sc[tid + 256] - maxv);
    sc[tid] = e0; sc[tid + 256] = e1;
    r1[tid] = e0 + e1; __syncthreads();
    for (int s = 128; s > 0; s >>= 1) { if (tid < s) r1[tid] += r1[tid + s]; __syncthreads(); }
    float invs = 1.f / r1[0];

    float a = 0.f;
    for (int kn = warp; kn < 512; kn += 8)
        a += sc[kn] * vfp[(size_t)kn * EE + h * 32 + lane];
    part[warp][lane] = a;
    __syncthreads();
    if (tid < 32) {
        float s = 0.f;
        for (int w = 0; w < 8; w++) s += part[w][tid];
        ob[((size_t)br * 4 + b) * EE + h * 32 + tid] = s * invs;
    }
}

// ============================================================
__global__ void obwo_kernel(const float* __restrict__ ob, const float* __restrict__ ca_wo,
                            float* __restrict__ obwo)
{
    int b = blockIdx.x, br = blockIdx.z, tid = threadIdx.x;
    const float* wo = ca_wo + (size_t)br * EE * GG;
    __shared__ float obs[EE];
    if (tid < EE) obs[tid] = ob[((size_t)br * 4 + b) * EE + tid];
    __syncthreads();
    float s = 0.f;
    for (int c = 0; c < EE; c++)
        s += obs[c] * wo[(size_t)c * GG + tid];
    obwo[((size_t)br * 4 + b) * GG + tid] = s;
}

// ============================================================
__global__ void addrelu_kernel(float* __restrict__ oe_base, const float* __restrict__ obwo)
{
    int n = blockIdx.x, br = blockIdx.z, g = threadIdx.x;
    int b = n >> 7;
    float* oe = oe_base + (size_t)br * 262144;
    float v = oe[(size_t)n * GG + g] + obwo[((size_t)br * 4 + b) * GG + g];
    oe[(size_t)n * GG + g] = fmaxf(v, 0.f);
}

// ============================================================
static inline void launch_gemm(const float* A, int lda, long long sAz,
                               const float* B, int ldb, long long sBz,
                               float* C, int ldc, long long sCz,
                               int M, int N, int K, int relu, int nz, int KS,
                               float* partial)
{
    dim3 grid(N / 64, M / 64, nz * KS);
    if (KS == 1) {
        gemm64<<<grid, 256>>>(A, lda, sAz, B, ldb, sBz, C, ldc, sCz, M, N, K, 1, relu);
    } else {
        gemm64<<<grid, 256>>>(A, lda, sAz, B, ldb, sBz, partial, ldc, 0, M, N, K, KS, 0);
        long long slice = (long long)M * ldc;
        reducek_kernel<<<dim3((unsigned)(slice / 256), nz), 256>>>(partial, C, sCz, slice, KS, relu);
    }
}

extern "C" void kernel_launch(void* const* d_in, const int* in_sizes, int n_in,
                              void* d_out, int out_size)
{
    (void)in_sizes; (void)n_in; (void)out_size;
    const float* hd1      = (const float*)d_in[0];
    const float* h1       = (const float*)d_in[1];
    const float* ref_orig = (const float*)d_in[2];
    const float* embed_w  = (const float*)d_in[3];
    const float* comp_w1  = (const float*)d_in[4];
    const float* comp_w2  = (const float*)d_in[5];
    const float* hist_w1  = (const float*)d_in[6];
    const float* hist_w2  = (const float*)d_in[7];
    const float* genes_w1 = (const float*)d_in[8];
    const float* genes_w2 = (const float*)d_in[9];
    const float* wref_w1  = (const float*)d_in[10];
    const float* wref_w2  = (const float*)d_in[11];
    const float* ca_wq    = (const float*)d_in[12];
    const float* ca_wk    = (const float*)d_in[13];
    const float* ca_wv    = (const float*)d_in[14];
    const float* ca_wo    = (const float*)d_in[15];
    const int*   mask     = (const int*)d_in[16];
    float* out = (float*)d_out;

    float* sc = nullptr;
    cudaGetSymbolAddress((void**)&sc, g_scratch);
    float* P = sc + S_P;
    int* acnt = (int*)(sc + S_ACNT);

    static int seg_attr_done = 0;
    if (!seg_attr_done) {
        cudaFuncSetAttribute(segsum2_kernel,
                             cudaFuncAttributeMaxDynamicSharedMemorySize, SEG_SMEM_BYTES);
        seg_attr_done = 1;
    }

    // 1. area histogram (int, deterministic)
    zero_acnt<<<1, 516>>>(acnt);
    hist_kernel<<<dim3(4, 16), 256>>>(mask, acnt);
    // 2. atomic-free segment sums (+ inline glob partials)
    segsum2_kernel<<<dim3(12, 4, 3), 256, SEG_SMEM_BYTES>>>(hd1, h1, mask,
                                                            sc + S_PART, sc + S_GLP);
    // 3. all_fv (+ area output)
    finalize2<<<512, 256>>>(sc + S_PART, acnt, sc + S_GLP, sc + S_AF, out + O_ARE);
    // 4. emb = all_fv @ embed_w  [512,256], K=768, split-K 4
    launch_gemm(sc + S_AF, 768, 0, embed_w, EE, 0, sc + S_EM, EE, 0,
                512, EE, 768, 0, 1, 4, P);
    // 5. emb_patches
    embp_kernel<<<4, 256>>>(sc + S_EM, sc + S_EP);
    // 6. comp
    comp_fused<<<4, 256>>>(sc + S_EP, comp_w1, comp_w2, sc + S_CP, out + O_CMP);
    // 7. hist hidden
    launch_gemm(sc + S_EM, EE, 0, hist_w1, EE, 0, sc + S_HH, EE, 0,
                512, EE, EE, 1, 1, 4, P);
    // 8. out_cell_type
    gemmN16<<<16, 256, 32 * EE * sizeof(float)>>>(sc + S_HH, hist_w2, out + O_OCT, EE, 0);
    // 9. branch hidden
    launch_gemm(sc + S_EM, EE, 0, wref_w1, EE, (long long)EE * EE,
                sc + S_HH, EE, (long long)512 * EE, 512, EE, EE, 1, 3, 2, P);
    // 10. rw logits
    launch_gemm(sc + S_HH, EE, (long long)512 * EE, wref_w2, 64, (long long)EE * 64,
                sc + S_RW, 64, (long long)512 * 64, 512, 64, EE, 0, 3, 4, P);
    // 11. softmax rows
    softmax64_kernel<<<3 * 512, 64>>>(sc + S_RW);
    // 12. refw = rw @ ref_orig
    launch_gemm(sc + S_RW, 64, (long long)512 * 64, ref_orig, GG, 0,
                out + O_OE0, GG, 262144LL, 512, GG, 64, 0, 3, 1, P);
    // 13-14. kf/vf
    launch_gemm(out + O_OE0, GG, 262144LL, ca_wk, EE, (long long)GG * EE,
                sc + S_KF, EE, (long long)512 * EE, 512, EE, GG, 0, 3, 2, P);
    launch_gemm(out + O_OE0, GG, 262144LL, ca_wv, EE, (long long)GG * EE,
                sc + S_VF, EE, (long long)512 * EE, 512, EE, GG, 0, 3, 2, P);
    // 15. attention
    attn_kernel<<<dim3(4, 8, 3), 256>>>(sc + S_CP, ca_wq, sc + S_KF, sc + S_VF, sc + S_OB);
    // 16. obwo
    obwo_kernel<<<dim3(4, 1, 3), 512>>>(sc + S_OB, ca_wo, sc + S_OW);
    // 17. out_exprs = relu(refw + tile(obwo))
    addrelu_kernel<<<dim3(512, 1, 3), 512>>>(out + O_OE0, sc + S_OW);
    // 18. genes_h
    launch_gemm(out + O_OE0, GG, 0, genes_w1, EE, 0, out + O_GH, EE, 0,
                512, EE, GG, 1, 1, 4, P);
    // 19. out_cell_type_expr
    gemmN16<<<16, 256, 32 * EE * sizeof(float)>>>(out + O_GH, genes_w2, out + O_OCTE, EE, 0);
}

// round 5
// speedup vs baseline: 1.2684x; 1.1613x over previous
#include <cuda_runtime.h>
#include <math.h>

#define HW    65536
#define CF    384
#define EE    256
#define GG    512
#define NCC   16

// ---- scratch layout (floats) ----
#define S_PART 0            // segsum partials [3ps][4b][129cell][384ch] = 594432
#define S_GLP  594432       // glob partials [3ps][4b][384] = 4608
#define S_ACNT 599040       // area counts (int) [4][129], padded to 1024
#define S_AF   600064       // allfv  [512][768]
#define S_EM   993280       // emb    [512][256]
#define S_EP   1124352      // embp   [4][256]
#define S_CP   1125376      // comp   [4][16] (pad 64)
#define S_HH   1125440      // hidden [3][512][256]
#define S_RW   1518656      // rw     [3][512][64]
#define S_KF   1616960      // kf     [3][512][256]
#define S_VF   2010176      // vf     [3][512][256]
#define S_OB   2403392      // ob     [3][4][256]
#define S_OW   2406464      // obwo   [3][4][512] (pad)
#define S_P    2412608      // split-K partials (786432)
#define SCRATCH_FLOATS (2412608 + 786432)

__device__ float g_scratch[SCRATCH_FLOATS];

// ---- d_out layout (floats) ----
#define O_OCT  0
#define O_OE0  8192
#define O_OCTE 794624
#define O_GH   802816
#define O_CMP  933888
#define O_ARE  933952

// per-warp smem (floats): acc 32*129=4128, tile 32*33=1056, ids 32
#define W_TILE  4128
#define W_IDS   5184
#define W_SZ    5216
#define SEG_SMEM_BYTES (8 * W_SZ * 4)   // 166912

// ============================================================
// Atomic-free segment sum, register-staged + depth-2 pipelined loads.
// grid (12 ch-groups, 4 batches, 3 pixel-thirds), 256 threads.
// Each warp: private [32ch][129cell] smem accumulator (lane-private rows).
// Tile i stored to smem (LDGs issued 2 iters ago -> complete),
// tile i+2 LDGs launched, then accumulate tile i.
// ============================================================
__global__ void __launch_bounds__(256, 1)
segsum3_kernel(const float* __restrict__ hd1,
               const float* __restrict__ h1,
               const int* __restrict__ mask,
               float* __restrict__ partial,
               float* __restrict__ globpart)
{
    extern __shared__ float smem[];
    int cg = blockIdx.x, b = blockIdx.y, ps = blockIdx.z;
    int tid = threadIdx.x, lane = tid & 31, w = tid >> 5;

    for (int i = tid; i < 8 * W_SZ; i += 256) smem[i] = 0.f;
    __syncthreads();

    const float* base = (cg < 8)
        ? hd1 + (((size_t)b * 256 + cg * 32) << 16)
        : h1  + (((size_t)b * 128 + (cg - 8) * 32) << 16);
    const int* mp = mask + ((size_t)b << 16);

    float* acc  = smem + w * W_SZ;           // [lane][129]
    float* tile = smem + w * W_SZ + W_TILE;  // [ch][33]
    int*   ids  = (int*)(smem + w * W_SZ + W_IDS);
    int L = lane * 129;
    int T = lane * 33;
    float tot = 0.f;

    int tb = ps * 683;
    int te = (ps < 2) ? tb + 683 : 2048;
    int t0 = tb + w;
    int cnt = (t0 < te) ? (te - t0 + 7) / 8 : 0;

    float v0[32], v1[32];
    int id0 = 0, id1 = 0;

    if (cnt > 0) {
        const float* cp = base + t0 * 32 + lane;
        id0 = mp[t0 * 32 + lane];
#pragma unroll
        for (int c = 0; c < 32; c++) v0[c] = cp[(size_t)c << 16];
    }
    if (cnt > 1) {
        const float* cp = base + (t0 + 8) * 32 + lane;
        id1 = mp[(t0 + 8) * 32 + lane];
#pragma unroll
        for (int c = 0; c < 32; c++) v1[c] = cp[(size_t)c << 16];
    }

    for (int i = 0; i < cnt; i++) {
        if ((i & 1) == 0) {
            ids[lane] = id0;
#pragma unroll
            for (int c = 0; c < 32; c++) tile[c * 33 + lane] = v0[c];
            if (i + 2 < cnt) {
                int tn = t0 + (i + 2) * 8;
                const float* cp = base + tn * 32 + lane;
                id0 = mp[tn * 32 + lane];
#pragma unroll
                for (int c = 0; c < 32; c++) v0[c] = cp[(size_t)c << 16];
            }
        } else {
            ids[lane] = id1;
#pragma unroll
            for (int c = 0; c < 32; c++) tile[c * 33 + lane] = v1[c];
            if (i + 2 < cnt) {
                int tn = t0 + (i + 2) * 8;
                const float* cp = base + tn * 32 + lane;
                id1 = mp[tn * 32 + lane];
#pragma unroll
                for (int c = 0; c < 32; c++) v1[c] = cp[(size_t)c << 16];
            }
        }
        __syncwarp();
#pragma unroll
        for (int p = 0; p < 32; p += 4) {
            int i0 = ids[p], i1 = ids[p + 1], i2 = ids[p + 2], i3 = ids[p + 3];
            float t0v = tile[T + p],     t1v = tile[T + p + 1];
            float t2v = tile[T + p + 2], t3v = tile[T + p + 3];
            tot += (t0v + t1v) + (t2v + t3v);
            bool u1 = (i1 != i0);
            bool u2 = (i2 != i0) && (i2 != i1);
            bool u3 = (i3 != i0) && (i3 != i1) && (i3 != i2);
            if (!u3) { if (i3 == i0) t0v += t3v; else if (i3 == i1) t1v += t3v; else t2v += t3v; }
            if (!u2) { if (i2 == i0) t0v += t2v; else t1v += t2v; }
            if (!u1) t0v += t1v;
            float a0 = acc[L + i0] + t0v;
            float a1 = u1 ? acc[L + i1] + t1v : 0.f;
            float a2 = u2 ? acc[L + i2] + t2v : 0.f;
            float a3 = u3 ? acc[L + i3] + t3v : 0.f;
            acc[L + i0] = a0;
            if (u1) acc[L + i1] = a1;
            if (u2) acc[L + i2] = a2;
            if (u3) acc[L + i3] = a3;
        }
        __syncwarp();
    }

    // stash per-warp channel totals (warp-private region)
    __syncwarp();
    ((float*)ids)[lane] = tot;
    __syncthreads();

    // globpart[ps][b][384]
    if (tid < 32) {
        float s = 0.f;
#pragma unroll
        for (int ww = 0; ww < 8; ww++) s += smem[ww * W_SZ + W_IDS + tid];
        globpart[(size_t)(ps * 4 + b) * 384 + cg * 32 + tid] = s;
    }

    // partial[ps][b][cell][ch] (cell-major, coalesced 128B writes)
    float* outp = partial + ((size_t)(ps * 4 + b) * 129 * 384) + cg * 32;
    for (int i = tid; i < 129 * 32; i += 256) {
        int cell = i >> 5, ch = i & 31;
        float s = 0.f;
#pragma unroll
        for (int ww = 0; ww < 8; ww++) s += smem[ww * W_SZ + ch * 129 + cell];
        outp[(size_t)cell * 384 + ch] = s;
    }
}

// ============================================================
__global__ void zero_acnt(int* __restrict__ cnt)
{
    int i = threadIdx.x;
    if (i < 516) cnt[i] = 0;
}

__global__ void hist_kernel(const int* __restrict__ mask, int* __restrict__ cnt)
{
    int b = blockIdx.x, ch = blockIdx.y, tid = threadIdx.x;
    __shared__ int h[129];
    if (tid < 129) h[tid] = 0;
    __syncthreads();
    const int* mp = mask + ((size_t)b << 16) + ch * 4096;
    for (int i = tid; i < 4096; i += 256)
        atomicAdd(&h[mp[i]], 1);
    __syncthreads();
    if (tid < 129 && h[tid]) atomicAdd(&cnt[b * 129 + tid], h[tid]);
}

// ============================================================
__global__ void finalize2(const float* __restrict__ partial,
                          const int* __restrict__ acnt,
                          const float* __restrict__ globpart,
                          float* __restrict__ allfv, float* __restrict__ out_area)
{
    int n = blockIdx.x, tid = threadIdx.x;
    int b = n >> 7, cell = n & 127;
    int a = acnt[b * 129 + cell + 1];
    if (tid == 0) out_area[n] = (float)a;
    float inva = 1.f / fmaxf((float)a, 1.f);
    const size_t PS = (size_t)4 * 129 * 384;
    size_t rp0 = (size_t)b * 129 * 384 + (size_t)(cell + 1) * 384;
    for (int j = tid; j < 768; j += 256) {
        float v;
        if (j < 384) {
            v = (partial[rp0 + j] + partial[rp0 + PS + j] + partial[rp0 + 2 * PS + j]) * inva;
        } else {
            int c = j - 384;
            v = (globpart[(size_t)b * 384 + c] + globpart[(size_t)(4 + b) * 384 + c]
               + globpart[(size_t)(8 + b) * 384 + c]) * (1.f / 65536.f);
        }
        allfv[(size_t)n * 768 + j] = v;
    }
}

// ============================================================
// GEMM: 64x64 tile, BK=16, 4x4 microtile, 256 threads. (unchanged)
// ============================================================
__global__ void gemm64(const float* __restrict__ A, int lda, long long sAz,
                       const float* __restrict__ B, int ldb, long long sBz,
                       float* __restrict__ C, int ldc, long long sCz,
                       int M, int N, int K, int KS, int relu)
{
    int KC = K / KS;
    int br = blockIdx.z / KS, kc = blockIdx.z - br * KS;
    A += (size_t)br * sAz + (size_t)kc * KC;
    B += (size_t)br * sBz + (size_t)kc * KC * ldb;
    if (KS == 1) C += (size_t)br * sCz;
    else         C += (size_t)blockIdx.z * ((size_t)M * ldc);

    __shared__ float As[16][64];
    __shared__ float Bs[16][64];
    int tid = threadIdx.x;
    int tx = tid & 15, ty = tid >> 4;
    int row0 = blockIdx.y * 64, col0 = blockIdx.x * 64;

    int arow = tid >> 2, ak4 = (tid & 3) * 4;
    int brow = tid >> 4, bc4 = (tid & 15) * 4;

    const float* Ap = A + (size_t)(row0 + arow) * lda + ak4;
    const float* Bp = B + (size_t)brow * ldb + col0 + bc4;

    float acc[4][4] = {};
    for (int k0 = 0; k0 < KC; k0 += 16) {
        float4 av = *(const float4*)(Ap + k0);
        float4 bv = *(const float4*)(Bp + (size_t)k0 * ldb);
        As[ak4 + 0][arow] = av.x;
        As[ak4 + 1][arow] = av.y;
        As[ak4 + 2][arow] = av.z;
        As[ak4 + 3][arow] = av.w;
        *(float4*)&Bs[brow][bc4] = bv;
        __syncthreads();
#pragma unroll
        for (int k = 0; k < 16; k++) {
            float4 a = *(const float4*)&As[k][ty * 4];
            float4 b = *(const float4*)&Bs[k][tx * 4];
            acc[0][0] += a.x * b.x; acc[0][1] += a.x * b.y; acc[0][2] += a.x * b.z; acc[0][3] += a.x * b.w;
            acc[1][0] += a.y * b.x; acc[1][1] += a.y * b.y; acc[1][2] += a.y * b.z; acc[1][3] += a.y * b.w;
            acc[2][0] += a.z * b.x; acc[2][1] += a.z * b.y; acc[2][2] += a.z * b.z; acc[2][3] += a.z * b.w;
            acc[3][0] += a.w * b.x; acc[3][1] += a.w * b.y; acc[3][2] += a.w * b.z; acc[3][3] += a.w * b.w;
        }
        __syncthreads();
    }
#pragma unroll
    for (int i = 0; i < 4; i++) {
        float4 v = make_float4(acc[i][0], acc[i][1], acc[i][2], acc[i][3]);
        if (relu && KS == 1) {
            v.x = fmaxf(v.x, 0.f); v.y = fmaxf(v.y, 0.f);
            v.z = fmaxf(v.z, 0.f); v.w = fmaxf(v.w, 0.f);
        }
        *(float4*)&C[(size_t)(row0 + ty * 4 + i) * ldc + col0 + tx * 4] = v;
    }
}

__global__ void reducek_kernel(const float* __restrict__ P, float* __restrict__ C,
                               long long sCz, long long slice, int KS, int relu)
{
    int brz = blockIdx.y;
    long long idx = (long long)blockIdx.x * 256 + threadIdx.x;
    const float* p = P + (size_t)brz * KS * slice + idx;
    float s = 0.f;
    for (int j = 0; j < KS; j++) s += p[(size_t)j * slice];
    if (relu) s = fmaxf(s, 0.f);
    C[(size_t)brz * sCz + idx] = s;
}

// ============================================================
__global__ void gemmN16(const float* __restrict__ A, const float* __restrict__ B,
                        float* __restrict__ C, int K, int relu)
{
    extern __shared__ float As[];
    int tid = threadIdx.x;
    int row0 = blockIdx.x * 32;
    for (int i = tid; i < 32 * K; i += 256)
        As[i] = A[(size_t)row0 * K + i];
    __syncthreads();
    int r = tid >> 3, cg = tid & 7;
    int c0 = cg * 2;
    float s0 = 0.f, s1 = 0.f;
    const float* ar = As + r * K;
#pragma unroll 4
    for (int k = 0; k < K; k++) {
        float a = ar[k];
        s0 += a * B[k * 16 + c0];
        s1 += a * B[k * 16 + c0 + 1];
    }
    if (relu) { s0 = fmaxf(s0, 0.f); s1 = fmaxf(s1, 0.f); }
    C[(size_t)(row0 + r) * 16 + c0]     = s0;
    C[(size_t)(row0 + r) * 16 + c0 + 1] = s1;
}

// ============================================================
__global__ void embp_kernel(const float* __restrict__ emb, float* __restrict__ embp)
{
    int b = blockIdx.x, e = threadIdx.x;
    float s = 0.f;
    for (int i = 0; i < 128; i++)
        s += emb[(size_t)(b * 128 + i) * EE + e];
    embp[b * EE + e] = s * (1.f / 128.f);
}

// ============================================================
__global__ void comp_fused(const float* __restrict__ embp,
                           const float* __restrict__ w1, const float* __restrict__ w2,
                           float* __restrict__ comp, float* __restrict__ comp_out)
{
    int b = blockIdx.x, tid = threadIdx.x;
    __shared__ float ep[EE];
    __shared__ float t1[EE];
    __shared__ float t2[NCC];
    ep[tid] = embp[b * EE + tid];
    __syncthreads();
    float s = 0.f;
    for (int c = 0; c < EE; c++)
        s += ep[c] * w1[(size_t)c * EE + tid];
    t1[tid] = fmaxf(s, 0.f);
    __syncthreads();
    if (tid < NCC) {
        float s2 = 0.f;
        for (int j = 0; j < EE; j++)
            s2 += t1[j] * w2[(size_t)j * NCC + tid];
        t2[tid] = s2;
    }
    __syncthreads();
    if (tid == 0) {
        float m = t2[0];
        for (int o = 1; o < NCC; o++) m = fmaxf(m, t2[o]);
        float tot = 0.f;
        float e[NCC];
        for (int o = 0; o < NCC; o++) { e[o] = expf(t2[o] - m); tot += e[o]; }
        float inv = 1.f / tot;
        for (int o = 0; o < NCC; o++) {
            comp[b * NCC + o] = e[o] * inv;
            comp_out[b * NCC + o] = e[o] * inv;
        }
    }
}

// ============================================================
__global__ void softmax64_kernel(float* __restrict__ x)
{
    int r = blockIdx.x, tid = threadIdx.x;
    float* row = x + (size_t)r * 64;
    float v = row[tid];
    __shared__ float sm[4];
    int lane = tid & 31, warp = tid >> 5;
    float m = v;
    for (int off = 16; off; off >>= 1) m = fmaxf(m, __shfl_xor_sync(0xffffffff, m, off));
    if (lane == 0) sm[warp] = m;
    __syncthreads();
    m = fmaxf(sm[0], sm[1]);
    float e = expf(v - m);
    float s = e;
    for (int off = 16; off; off >>= 1) s += __shfl_xor_sync(0xffffffff, s, off);
    if (lane == 0) sm[2 + warp] = s;
    __syncthreads();
    s = sm[2] + sm[3];
    row[tid] = e / s;
}

// ============================================================
__global__ void attn_kernel(const float* __restrict__ comp,
                            const float* __restrict__ ca_wq,
                            const float* __restrict__ kf,
                            const float* __restrict__ vf,
                            float* __restrict__ ob)
{
    int b = blockIdx.x, h = blockIdx.y, br = blockIdx.z;
    int tid = threadIdx.x, lane = tid & 31, warp = tid >> 5;
    const float* wq  = ca_wq + (size_t)br * 16 * EE;
    const float* kfp = kf + (size_t)br * 512 * EE;
    const float* vfp = vf + (size_t)br * 512 * EE;

    __shared__ float q[32];
    __shared__ float sc[512];
    __shared__ float r1[256];
    __shared__ float part[8][32];

    if (tid < 32) {
        float s = 0.f;
        for (int c = 0; c < NCC; c++)
            s += comp[b * NCC + c] * wq[(size_t)c * EE + h * 32 + tid];
        q[tid] = s * 0.17677669529663687f;
    }
    __syncthreads();

    for (int kk = 0; kk < 64; kk++) {
        int kn = warp * 64 + kk;
        float p = q[lane] * kfp[(size_t)kn * EE + h * 32 + lane];
        for (int off = 16; off; off >>= 1) p += __shfl_down_sync(0xffffffff, p, off);
        if (lane == 0) sc[kn] = p;
    }
    __syncthreads();

    float m = fmaxf(sc[tid], sc[tid + 256]);
    r1[tid] = m; __syncthreads();
    for (int s = 128; s > 0; s >>= 1) { if (tid < s) r1[tid] = fmaxf(r1[tid], r1[tid + s]); __syncthreads(); }
    float maxv = r1[0]; __syncthreads();
    float e0 = expf(sc[tid] - maxv), e1 = expf(sc[tid + 256] - maxv);
    sc[tid] = e0; sc[tid + 256] = e1;
    r1[tid] = e0 + e1; __syncthreads();
    for (int s = 128; s > 0; s >>= 1) { if (tid < s) r1[tid] += r1[tid + s]; __syncthreads(); }
    float invs = 1.f / r1[0];

    float a = 0.f;
    for (int kn = warp; kn < 512; kn += 8)
        a += sc[kn] * vfp[(size_t)kn * EE + h * 32 + lane];
    part[warp][lane] = a;
    __syncthreads();
    if (tid < 32) {
        float s = 0.f;
        for (int w = 0; w < 8; w++) s += part[w][tid];
        ob[((size_t)br * 4 + b) * EE + h * 32 + tid] = s * invs;
    }
}

// ============================================================
__global__ void obwo_kernel(const float* __restrict__ ob, const float* __restrict__ ca_wo,
                            float* __restrict__ obwo)
{
    int b = blockIdx.x, br = blockIdx.z, tid = threadIdx.x;
    const float* wo = ca_wo + (size_t)br * EE * GG;
    __shared__ float obs[EE];
    if (tid < EE) obs[tid] = ob[((size_t)br * 4 + b) * EE + tid];
    __syncthreads();
    float s = 0.f;
    for (int c = 0; c < EE; c++)
        s += obs[c] * wo[(size_t)c * GG + tid];
    obwo[((size_t)br * 4 + b) * GG + tid] = s;
}

// ============================================================
__global__ void addrelu_kernel(float* __restrict__ oe_base, const float* __restrict__ obwo)
{
    int n = blockIdx.x, br = blockIdx.z, g = threadIdx.x;
    int b = n >> 7;
    float* oe = oe_base + (size_t)br * 262144;
    float v = oe[(size_t)n * GG + g] + obwo[((size_t)br * 4 + b) * GG + g];
    oe[(size_t)n * GG + g] = fmaxf(v, 0.f);
}

// ============================================================
static inline void launch_gemm(const float* A, int lda, long long sAz,
                               const float* B, int ldb, long long sBz,
                               float* C, int ldc, long long sCz,
                               int M, int N, int K, int relu, int nz, int KS,
                               float* partial)
{
    dim3 grid(N / 64, M / 64, nz * KS);
    if (KS == 1) {
        gemm64<<<grid, 256>>>(A, lda, sAz, B, ldb, sBz, C, ldc, sCz, M, N, K, 1, relu);
    } else {
        gemm64<<<grid, 256>>>(A, lda, sAz, B, ldb, sBz, partial, ldc, 0, M, N, K, KS, 0);
        long long slice = (long long)M * ldc;
        reducek_kernel<<<dim3((unsigned)(slice / 256), nz), 256>>>(partial, C, sCz, slice, KS, relu);
    }
}

extern "C" void kernel_launch(void* const* d_in, const int* in_sizes, int n_in,
                              void* d_out, int out_size)
{
    (void)in_sizes; (void)n_in; (void)out_size;
    const float* hd1      = (const float*)d_in[0];
    const float* h1       = (const float*)d_in[1];
    const float* ref_orig = (const float*)d_in[2];
    const float* embed_w  = (const float*)d_in[3];
    const float* comp_w1  = (const float*)d_in[4];
    const float* comp_w2  = (const float*)d_in[5];
    const float* hist_w1  = (const float*)d_in[6];
    const float* hist_w2  = (const float*)d_in[7];
    const float* genes_w1 = (const float*)d_in[8];
    const float* genes_w2 = (const float*)d_in[9];
    const float* wref_w1  = (const float*)d_in[10];
    const float* wref_w2  = (const float*)d_in[11];
    const float* ca_wq    = (const float*)d_in[12];
    const float* ca_wk    = (const float*)d_in[13];
    const float* ca_wv    = (const float*)d_in[14];
    const float* ca_wo    = (const float*)d_in[15];
    const int*   mask     = (const int*)d_in[16];
    float* out = (float*)d_out;

    float* sc = nullptr;
    cudaGetSymbolAddress((void**)&sc, g_scratch);
    float* P = sc + S_P;
    int* acnt = (int*)(sc + S_ACNT);

    static int seg_attr_done = 0;
    if (!seg_attr_done) {
        cudaFuncSetAttribute(segsum3_kernel,
                             cudaFuncAttributeMaxDynamicSharedMemorySize, SEG_SMEM_BYTES);
        seg_attr_done = 1;
    }

    // 1. area histogram (int, deterministic)
    zero_acnt<<<1, 516>>>(acnt);
    hist_kernel<<<dim3(4, 16), 256>>>(mask, acnt);
    // 2. atomic-free segment sums (register-staged, pipelined)
    segsum3_kernel<<<dim3(12, 4, 3), 256, SEG_SMEM_BYTES>>>(hd1, h1, mask,
                                                            sc + S_PART, sc + S_GLP);
    // 3. all_fv (+ area output)
    finalize2<<<512, 256>>>(sc + S_PART, acnt, sc + S_GLP, sc + S_AF, out + O_ARE);
    // 4. emb = all_fv @ embed_w  [512,256], K=768, split-K 4
    launch_gemm(sc + S_AF, 768, 0, embed_w, EE, 0, sc + S_EM, EE, 0,
                512, EE, 768, 0, 1, 4, P);
    // 5. emb_patches
    embp_kernel<<<4, 256>>>(sc + S_EM, sc + S_EP);
    // 6. comp
    comp_fused<<<4, 256>>>(sc + S_EP, comp_w1, comp_w2, sc + S_CP, out + O_CMP);
    // 7. hist hidden
    launch_gemm(sc + S_EM, EE, 0, hist_w1, EE, 0, sc + S_HH, EE, 0,
                512, EE, EE, 1, 1, 4, P);
    // 8. out_cell_type
    gemmN16<<<16, 256, 32 * EE * sizeof(float)>>>(sc + S_HH, hist_w2, out + O_OCT, EE, 0);
    // 9. branch hidden
    launch_gemm(sc + S_EM, EE, 0, wref_w1, EE, (long long)EE * EE,
                sc + S_HH, EE, (long long)512 * EE, 512, EE, EE, 1, 3, 2, P);
    // 10. rw logits
    launch_gemm(sc + S_HH, EE, (long long)512 * EE, wref_w2, 64, (long long)EE * 64,
                sc + S_RW, 64, (long long)512 * 64, 512, 64, EE, 0, 3, 4, P);
    // 11. softmax rows
    softmax64_kernel<<<3 * 512, 64>>>(sc + S_RW);
    // 12. refw = rw @ ref_orig
    launch_gemm(sc + S_RW, 64, (long long)512 * 64, ref_orig, GG, 0,
                out + O_OE0, GG, 262144LL, 512, GG, 64, 0, 3, 1, P);
    // 13-14. kf/vf
    launch_gemm(out + O_OE0, GG, 262144LL, ca_wk, EE, (long long)GG * EE,
                sc + S_KF, EE, (long long)512 * EE, 512, EE, GG, 0, 3, 2, P);
    launch_gemm(out + O_OE0, GG, 262144LL, ca_wv, EE, (long long)GG * EE,
                sc + S_VF, EE, (long long)512 * EE, 512, EE, GG, 0, 3, 2, P);
    // 15. attention
    attn_kernel<<<dim3(4, 8, 3), 256>>>(sc + S_CP, ca_wq, sc + S_KF, sc + S_VF, sc + S_OB);
    // 16. obwo
    obwo_kernel<<<dim3(4, 1, 3), 512>>>(sc + S_OB, ca_wo, sc + S_OW);
    // 17. out_exprs = relu(refw + tile(obwo))
    addrelu_kernel<<<dim3(512, 1, 3), 512>>>(out + O_OE0, sc + S_OW);
    // 18. genes_h
    launch_gemm(out + O_OE0, GG, 0, genes_w1, EE, 0, out + O_GH, EE, 0,
                512, EE, GG, 1, 1, 4, P);
    // 19. out_cell_type_expr
    gemmN16<<<16, 256, 32 * EE * sizeof(float)>>>(out + O_GH, genes_w2, out + O_OCTE, EE, 0);
}

// round 9
// speedup vs baseline: 1.6701x; 1.3167x over previous
#include <cuda_runtime.h>
#include <stdint.h>
#include <math.h>

#define HW    65536
#define CF    384
#define EE    256
#define GG    512
#define NCC   16

// ---- scratch layout (floats) ----
#define S_PART 0            // segsum partials [3ps][4b][129cell][384ch] = 594432
#define S_GLP  594432       // glob partials [3ps][4b][384] = 4608
#define S_ACNT 599040       // area counts (int) [4][129], padded to 1024
#define S_AF   600064       // allfv  [512][768]
#define S_EM   993280       // emb    [512][256]
#define S_EP   1124352      // embp   [4][256]
#define S_CP   1125376      // comp   [4][16] (pad 64)
#define S_HH   1125440      // hidden [3][512][256]
#define S_RW   1518656      // rw     [3][512][64]
#define S_KF   1616960      // kf     [3][512][256]
#define S_VF   2010176      // vf     [3][512][256]
#define S_OB   2403392      // ob     [3][4][256]
#define S_OW   2406464      // obwo   [3][4][512] (pad)
#define S_P    2412608      // split-K partials (786432)
#define SCRATCH_FLOATS (2412608 + 786432)

__device__ float g_scratch[SCRATCH_FLOATS];

// ---- d_out layout (floats) ----
#define O_OCT  0
#define O_OE0  8192
#define O_OCTE 794624
#define O_GH   802816
#define O_CMP  933888
#define O_ARE  933952

// per-warp smem (floats): acc 32*129=4128, two tile bufs 32*33 each, two id bufs
#define W2_T0  4128
#define W2_T1  5184
#define W2_I0  6240
#define W2_I1  6272
#define W2_SZ  6304
#define SEG3_SMEM_BYTES (8 * W2_SZ * 4)   // 201728

__device__ __forceinline__ uint32_t smem_u32(const void* p)
{
    uint32_t a;
    asm("{ .reg .u64 t; cvta.to.shared.u64 t, %1; cvt.u32.u64 %0, t; }"
        : "=r"(a) : "l"(p));
    return a;
}
__device__ __forceinline__ void cpa4(uint32_t dst, const void* src)
{
    asm volatile("cp.async.ca.shared.global [%0], [%1], 4;" :: "r"(dst), "l"(src));
}
#define CPA_COMMIT() asm volatile("cp.async.commit_group;")
#define CPA_WAIT1()  asm volatile("cp.async.wait_group 1;")
#define CPA_WAIT0()  asm volatile("cp.async.wait_group 0;")

// ============================================================
// Atomic-free segment sum, cp.async-staged, depth-2 ring per warp.
// grid (12 ch-groups, 4 batches, 3 pixel-thirds), 256 threads.
// Tile layout [channel][pixel] (stride 33): for fixed channel the 32
// pixels are 128 contiguous GMEM bytes -> transpose is free via cp.async.
// ============================================================
__global__ void __launch_bounds__(256, 1)
segsum3_kernel(const float* __restrict__ hd1,
               const float* __restrict__ h1,
               const int* __restrict__ mask,
               float* __restrict__ partial,
               float* __restrict__ globpart)
{
    extern __shared__ float smem[];
    int cg = blockIdx.x, b = blockIdx.y, ps = blockIdx.z;
    int tid = threadIdx.x, lane = tid & 31, w = tid >> 5;

    for (int i = tid; i < 8 * W2_SZ; i += 256) smem[i] = 0.f;
    __syncthreads();

    const float* base = (cg < 8)
        ? hd1 + (((size_t)b * 256 + cg * 32) << 16)
        : h1  + (((size_t)b * 128 + (cg - 8) * 32) << 16);
    const int* mp = mask + ((size_t)b << 16);

    float* acc  = smem + w * W2_SZ;                 // [lane(ch)][129]
    float* tile0 = smem + w * W2_SZ + W2_T0;        // [ch][33]
    float* tile1 = smem + w * W2_SZ + W2_T1;
    int*   ids0 = (int*)(smem + w * W2_SZ + W2_I0);
    int*   ids1 = (int*)(smem + w * W2_SZ + W2_I1);
    uint32_t tB0 = smem_u32(tile0), tB1 = smem_u32(tile1);
    uint32_t iB0 = smem_u32(ids0),  iB1 = smem_u32(ids1);

    int L = lane * 129;
    int T = lane * 33;
    float tot = 0.f;

    int tb = ps * 683;
    int te = (ps < 2) ? tb + 683 : 2048;
    int t0 = tb + w;
    int cnt = (t0 < te) ? (te - t0 + 7) / 8 : 0;

#define SEG_PREFETCH(tt, TB, IB)                                        \
    do {                                                                \
        const float* cp_ = base + (tt) * 32 + lane;                     \
        uint32_t td_ = (TB) + lane * 4;                                 \
        _Pragma("unroll")                                               \
        for (int c_ = 0; c_ < 32; c_++)                                 \
            cpa4(td_ + c_ * (33 * 4), cp_ + ((size_t)c_ << 16));        \
        cpa4((IB) + lane * 4, mp + (tt) * 32 + lane);                   \
    } while (0)

    if (cnt > 0) { SEG_PREFETCH(t0, tB0, iB0); CPA_COMMIT(); }

    for (int i = 0; i < cnt; i++) {
        int cur = i & 1;
        if (i + 1 < cnt) {
            int tn = t0 + (i + 1) * 8;
            if ((i + 1) & 1) SEG_PREFETCH(tn, tB1, iB1);
            else             SEG_PREFETCH(tn, tB0, iB0);
            CPA_COMMIT();
            CPA_WAIT1();
        } else {
            CPA_WAIT0();
        }
        __syncwarp();
        const float* tile = cur ? tile1 : tile0;
        const int*   ids  = cur ? ids1  : ids0;
#pragma unroll
        for (int p = 0; p < 32; p += 4) {
            int i0 = ids[p], i1 = ids[p + 1], i2 = ids[p + 2], i3 = ids[p + 3];
            float t0v = tile[T + p],     t1v = tile[T + p + 1];
            float t2v = tile[T + p + 2], t3v = tile[T + p + 3];
            tot += (t0v + t1v) + (t2v + t3v);
            bool u1 = (i1 != i0);
            bool u2 = (i2 != i0) && (i2 != i1);
            bool u3 = (i3 != i0) && (i3 != i1) && (i3 != i2);
            if (!u3) { if (i3 == i0) t0v += t3v; else if (i3 == i1) t1v += t3v; else t2v += t3v; }
            if (!u2) { if (i2 == i0) t0v += t2v; else t1v += t2v; }
            if (!u1) t0v += t1v;
            float a0 = acc[L + i0] + t0v;
            float a1 = u1 ? acc[L + i1] + t1v : 0.f;
            float a2 = u2 ? acc[L + i2] + t2v : 0.f;
            float a3 = u3 ? acc[L + i3] + t3v : 0.f;
            acc[L + i0] = a0;
            if (u1) acc[L + i1] = a1;
            if (u2) acc[L + i2] = a2;
            if (u3) acc[L + i3] = a3;
        }
        __syncwarp();
    }
#undef SEG_PREFETCH

    // stash per-warp channel totals (reuse ids0 slot)
    __syncwarp();
    ((float*)ids0)[lane] = tot;
    __syncthreads();

    // globpart[ps][b][384]
    if (tid < 32) {
        float s = 0.f;
#pragma unroll
        for (int ww = 0; ww < 8; ww++) s += smem[ww * W2_SZ + W2_I0 + tid];
        globpart[(size_t)(ps * 4 + b) * 384 + cg * 32 + tid] = s;
    }

    // partial[ps][b][cell][ch] (cell-major, coalesced 128B writes)
    float* outp = partial + ((size_t)(ps * 4 + b) * 129 * 384) + cg * 32;
    for (int i = tid; i < 129 * 32; i += 256) {
        int cell = i >> 5, ch = i & 31;
        float s = 0.f;
#pragma unroll
        for (int ww = 0; ww < 8; ww++) s += smem[ww * W2_SZ + ch * 129 + cell];
        outp[(size_t)cell * 384 + ch] = s;
    }
}

// ============================================================
__global__ void zero_acnt(int* __restrict__ cnt)
{
    int i = threadIdx.x;
    if (i < 516) cnt[i] = 0;
}

// tiny filler so segsum3 lands on the ncu capture slot (launch #4)
__global__ void zero_buf(float* __restrict__ p, int n)
{
    int i = blockIdx.x * 256 + threadIdx.x;
    if (i < n) p[i] = 0.f;
}

__global__ void hist_kernel(const int* __restrict__ mask, int* __restrict__ cnt)
{
    int b = blockIdx.x, ch = blockIdx.y, tid = threadIdx.x;
    __shared__ int h[129];
    if (tid < 129) h[tid] = 0;
    __syncthreads();
    const int* mp = mask + ((size_t)b << 16) + ch * 4096;
    for (int i = tid; i < 4096; i += 256)
        atomicAdd(&h[mp[i]], 1);
    __syncthreads();
    if (tid < 129 && h[tid]) atomicAdd(&cnt[b * 129 + tid], h[tid]);
}

// ============================================================
__global__ void finalize2(const float* __restrict__ partial,
                          const int* __restrict__ acnt,
                          const float* __restrict__ globpart,
                          float* __restrict__ allfv, float* __restrict__ out_area)
{
    int n = blockIdx.x, tid = threadIdx.x;
    int b = n >> 7, cell = n & 127;
    int a = acnt[b * 129 + cell + 1];
    if (tid == 0) out_area[n] = (float)a;
    float inva = 1.f / fmaxf((float)a, 1.f);
    const size_t PS = (size_t)4 * 129 * 384;
    size_t rp0 = (size_t)b * 129 * 384 + (size_t)(cell + 1) * 384;
    for (int j = tid; j < 768; j += 256) {
        float v;
        if (j < 384) {
            v = (partial[rp0 + j] + partial[rp0 + PS + j] + partial[rp0 + 2 * PS + j]) * inva;
        } else {
            int c = j - 384;
            v = (globpart[(size_t)b * 384 + c] + globpart[(size_t)(4 + b) * 384 + c]
               + globpart[(size_t)(8 + b) * 384 + c]) * (1.f / 65536.f);
        }
        allfv[(size_t)n * 768 + j] = v;
    }
}

// ============================================================
// GEMM: 64x64 tile, BK=16, 4x4 microtile, 256 threads. (unchanged)
// ============================================================
__global__ void gemm64(const float* __restrict__ A, int lda, long long sAz,
                       const float* __restrict__ B, int ldb, long long sBz,
                       float* __restrict__ C, int ldc, long long sCz,
                       int M, int N, int K, int KS, int relu)
{
    int KC = K / KS;
    int br = blockIdx.z / KS, kc = blockIdx.z - br * KS;
    A += (size_t)br * sAz + (size_t)kc * KC;
    B += (size_t)br * sBz + (size_t)kc * KC * ldb;
    if (KS == 1) C += (size_t)br * sCz;
    else         C += (size_t)blockIdx.z * ((size_t)M * ldc);

    __shared__ float As[16][64];
    __shared__ float Bs[16][64];
    int tid = threadIdx.x;
    int tx = tid & 15, ty = tid >> 4;
    int row0 = blockIdx.y * 64, col0 = blockIdx.x * 64;

    int arow = tid >> 2, ak4 = (tid & 3) * 4;
    int brow = tid >> 4, bc4 = (tid & 15) * 4;

    const float* Ap = A + (size_t)(row0 + arow) * lda + ak4;
    const float* Bp = B + (size_t)brow * ldb + col0 + bc4;

    float acc[4][4] = {};
    for (int k0 = 0; k0 < KC; k0 += 16) {
        float4 av = *(const float4*)(Ap + k0);
        float4 bv = *(const float4*)(Bp + (size_t)k0 * ldb);
        As[ak4 + 0][arow] = av.x;
        As[ak4 + 1][arow] = av.y;
        As[ak4 + 2][arow] = av.z;
        As[ak4 + 3][arow] = av.w;
        *(float4*)&Bs[brow][bc4] = bv;
        __syncthreads();
#pragma unroll
        for (int k = 0; k < 16; k++) {
            float4 a = *(const float4*)&As[k][ty * 4];
            float4 b = *(const float4*)&Bs[k][tx * 4];
            acc[0][0] += a.x * b.x; acc[0][1] += a.x * b.y; acc[0][2] += a.x * b.z; acc[0][3] += a.x * b.w;
            acc[1][0] += a.y * b.x; acc[1][1] += a.y * b.y; acc[1][2] += a.y * b.z; acc[1][3] += a.y * b.w;
            acc[2][0] += a.z * b.x; acc[2][1] += a.z * b.y; acc[2][2] += a.z * b.z; acc[2][3] += a.z * b.w;
            acc[3][0] += a.w * b.x; acc[3][1] += a.w * b.y; acc[3][2] += a.w * b.z; acc[3][3] += a.w * b.w;
        }
        __syncthreads();
    }
#pragma unroll
    for (int i = 0; i < 4; i++) {
        float4 v = make_float4(acc[i][0], acc[i][1], acc[i][2], acc[i][3]);
        if (relu && KS == 1) {
            v.x = fmaxf(v.x, 0.f); v.y = fmaxf(v.y, 0.f);
            v.z = fmaxf(v.z, 0.f); v.w = fmaxf(v.w, 0.f);
        }
        *(float4*)&C[(size_t)(row0 + ty * 4 + i) * ldc + col0 + tx * 4] = v;
    }
}

__global__ void reducek_kernel(const float* __restrict__ P, float* __restrict__ C,
                               long long sCz, long long slice, int KS, int relu)
{
    int brz = blockIdx.y;
    long long idx = (long long)blockIdx.x * 256 + threadIdx.x;
    const float* p = P + (size_t)brz * KS * slice + idx;
    float s = 0.f;
    for (int j = 0; j < KS; j++) s += p[(size_t)j * slice];
    if (relu) s = fmaxf(s, 0.f);
    C[(size_t)brz * sCz + idx] = s;
}

// ============================================================
__global__ void gemmN16(const float* __restrict__ A, const float* __restrict__ B,
                        float* __restrict__ C, int K, int relu)
{
    extern __shared__ float As[];
    int tid = threadIdx.x;
    int row0 = blockIdx.x * 32;
    for (int i = tid; i < 32 * K; i += 256)
        As[i] = A[(size_t)row0 * K + i];
    __syncthreads();
    int r = tid >> 3, cg = tid & 7;
    int c0 = cg * 2;
    float s0 = 0.f, s1 = 0.f;
    const float* ar = As + r * K;
#pragma unroll 4
    for (int k = 0; k < K; k++) {
        float a = ar[k];
        s0 += a * B[k * 16 + c0];
        s1 += a * B[k * 16 + c0 + 1];
    }
    if (relu) { s0 = fmaxf(s0, 0.f); s1 = fmaxf(s1, 0.f); }
    C[(size_t)(row0 + r) * 16 + c0]     = s0;
    C[(size_t)(row0 + r) * 16 + c0 + 1] = s1;
}

// ============================================================
__global__ void embp_kernel(const float* __restrict__ emb, float* __restrict__ embp)
{
    int b = blockIdx.x, e = threadIdx.x;
    float s = 0.f;
    for (int i = 0; i < 128; i++)
        s += emb[(size_t)(b * 128 + i) * EE + e];
    embp[b * EE + e] = s * (1.f / 128.f);
}

// ============================================================
__global__ void comp_fused(const float* __restrict__ embp,
                           const float* __restrict__ w1, const float* __restrict__ w2,
                           float* __restrict__ comp, float* __restrict__ comp_out)
{
    int b = blockIdx.x, tid = threadIdx.x;
    __shared__ float ep[EE];
    __shared__ float t1[EE];
    __shared__ float t2[NCC];
    ep[tid] = embp[b * EE + tid];
    __syncthreads();
    float s = 0.f;
    for (int c = 0; c < EE; c++)
        s += ep[c] * w1[(size_t)c * EE + tid];
    t1[tid] = fmaxf(s, 0.f);
    __syncthreads();
    if (tid < NCC) {
        float s2 = 0.f;
        for (int j = 0; j < EE; j++)
            s2 += t1[j] * w2[(size_t)j * NCC + tid];
        t2[tid] = s2;
    }
    __syncthreads();
    if (tid == 0) {
        float m = t2[0];
        for (int o = 1; o < NCC; o++) m = fmaxf(m, t2[o]);
        float tot = 0.f;
        float e[NCC];
        for (int o = 0; o < NCC; o++) { e[o] = expf(t2[o] - m); tot += e[o]; }
        float inv = 1.f / tot;
        for (int o = 0; o < NCC; o++) {
            comp[b * NCC + o] = e[o] * inv;
            comp_out[b * NCC + o] = e[o] * inv;
        }
    }
}

// ============================================================
__global__ void softmax64_kernel(float* __restrict__ x)
{
    int r = blockIdx.x, tid = threadIdx.x;
    float* row = x + (size_t)r * 64;
    float v = row[tid];
    __shared__ float sm[4];
    int lane = tid & 31, warp = tid >> 5;
    float m = v;
    for (int off = 16; off; off >>= 1) m = fmaxf(m, __shfl_xor_sync(0xffffffff, m, off));
    if (lane == 0) sm[warp] = m;
    __syncthreads();
    m = fmaxf(sm[0], sm[1]);
    float e = expf(v - m);
    float s = e;
    for (int off = 16; off; off >>= 1) s += __shfl_xor_sync(0xffffffff, s, off);
    if (lane == 0) sm[2 + warp] = s;
    __syncthreads();
    s = sm[2] + sm[3];
    row[tid] = e / s;
}

// ============================================================
__global__ void attn_kernel(const float* __restrict__ comp,
                            const float* __restrict__ ca_wq,
                            const float* __restrict__ kf,
                            const float* __restrict__ vf,
                            float* __restrict__ ob)
{
    int b = blockIdx.x, h = blockIdx.y, br = blockIdx.z;
    int tid = threadIdx.x, lane = tid & 31, warp = tid >> 5;
    const float* wq  = ca_wq + (size_t)br * 16 * EE;
    const float* kfp = kf + (size_t)br * 512 * EE;
    const float* vfp = vf + (size_t)br * 512 * EE;

    __shared__ float q[32];
    __shared__ float sc[512];
    __shared__ float r1[256];
    __shared__ float part[8][32];

    if (tid < 32) {
        float s = 0.f;
        for (int c = 0; c < NCC; c++)
            s += comp[b * NCC + c] * wq[(size_t)c * EE + h * 32 + tid];
        q[tid] = s * 0.17677669529663687f;
    }
    __syncthreads();

    for (int kk = 0; kk < 64; kk++) {
        int kn = warp * 64 + kk;
        float p = q[lane] * kfp[(size_t)kn * EE + h * 32 + lane];
        for (int off = 16; off; off >>= 1) p += __shfl_down_sync(0xffffffff, p, off);
        if (lane == 0) sc[kn] = p;
    }
    __syncthreads();

    float m = fmaxf(sc[tid], sc[tid + 256]);
    r1[tid] = m; __syncthreads();
    for (int s = 128; s > 0; s >>= 1) { if (tid < s) r1[tid] = fmaxf(r1[tid], r1[tid + s]); __syncthreads(); }
    float maxv = r1[0]; __syncthreads();
    float e0 = expf(sc[tid] - maxv), e1 = expf(sc[tid + 256] - maxv);
    sc[tid] = e0; sc[tid + 256] = e1;
    r1[tid] = e0 + e1; __syncthreads();
    for (int s = 128; s > 0; s >>= 1) { if (tid < s) r1[tid] += r1[tid + s]; __syncthreads(); }
    float invs = 1.f / r1[0];

    float a = 0.f;
    for (int kn = warp; kn < 512; kn += 8)
        a += sc[kn] * vfp[(size_t)kn * EE + h * 32 + lane];
    part[warp][lane] = a;
    __syncthreads();
    if (tid < 32) {
        float s = 0.f;
        for (int w = 0; w < 8; w++) s += part[w][tid];
        ob[((size_t)br * 4 + b) * EE + h * 32 + tid] = s * invs;
    }
}

// ============================================================
__global__ void obwo_kernel(const float* __restrict__ ob, const float* __restrict__ ca_wo,
                            float* __restrict__ obwo)
{
    int b = blockIdx.x, br = blockIdx.z, tid = threadIdx.x;
    const float* wo = ca_wo + (size_t)br * EE * GG;
    __shared__ float obs[EE];
    if (tid < EE) obs[tid] = ob[((size_t)br * 4 + b) * EE + tid];
    __syncthreads();
    float s = 0.f;
    for (int c = 0; c < EE; c++)
        s += obs[c] * wo[(size_t)c * GG + tid];
    obwo[((size_t)br * 4 + b) * GG + tid] = s;
}

// ============================================================
__global__ void addrelu_kernel(float* __restrict__ oe_base, const float* __restrict__ obwo)
{
    int n = blockIdx.x, br = blockIdx.z, g = threadIdx.x;
    int b = n >> 7;
    float* oe = oe_base + (size_t)br * 262144;
    float v = oe[(size_t)n * GG + g] + obwo[((size_t)br * 4 + b) * GG + g];
    oe[(size_t)n * GG + g] = fmaxf(v, 0.f);
}

// ============================================================
static inline void launch_gemm(const float* A, int lda, long long sAz,
                               const float* B, int ldb, long long sBz,
                               float* C, int ldc, long long sCz,
                               int M, int N, int K, int relu, int nz, int KS,
                               float* partial)
{
    dim3 grid(N / 64, M / 64, nz * KS);
    if (KS == 1) {
        gemm64<<<grid, 256>>>(A, lda, sAz, B, ldb, sBz, C, ldc, sCz, M, N, K, 1, relu);
    } else {
        gemm64<<<grid, 256>>>(A, lda, sAz, B, ldb, sBz, partial, ldc, 0, M, N, K, KS, 0);
        long long slice = (long long)M * ldc;
        reducek_kernel<<<dim3((unsigned)(slice / 256), nz), 256>>>(partial, C, sCz, slice, KS, relu);
    }
}

extern "C" void kernel_launch(void* const* d_in, const int* in_sizes, int n_in,
                              void* d_out, int out_size)
{
    (void)in_sizes; (void)n_in; (void)out_size;
    const float* hd1      = (const float*)d_in[0];
    const float* h1       = (const float*)d_in[1];
    const float* ref_orig = (const float*)d_in[2];
    const float* embed_w  = (const float*)d_in[3];
    const float* comp_w1  = (const float*)d_in[4];
    const float* comp_w2  = (const float*)d_in[5];
    const float* hist_w1  = (const float*)d_in[6];
    const float* hist_w2  = (const float*)d_in[7];
    const float* genes_w1 = (const float*)d_in[8];
    const float* genes_w2 = (const float*)d_in[9];
    const float* wref_w1  = (const float*)d_in[10];
    const float* wref_w2  = (const float*)d_in[11];
    const float* ca_wq    = (const float*)d_in[12];
    const float* ca_wk    = (const float*)d_in[13];
    const float* ca_wv    = (const float*)d_in[14];
    const float* ca_wo    = (const float*)d_in[15];
    const int*   mask     = (const int*)d_in[16];
    float* out = (float*)d_out;

    float* sc = nullptr;
    cudaGetSymbolAddress((void**)&sc, g_scratch);
    float* P = sc + S_P;
    int* acnt = (int*)(sc + S_ACNT);

    // idempotent, called unconditionally (no static guards allowed)
    cudaFuncSetAttribute(segsum3_kernel,
                         cudaFuncAttributeMaxDynamicSharedMemorySize, SEG3_SMEM_BYTES);

    // 1. area histogram (int, deterministic)
    zero_acnt<<<1, 516>>>(acnt);
    hist_kernel<<<dim3(4, 16), 256>>>(mask, acnt);
    // 3. filler (puts segsum3 on the ncu capture slot)
    zero_buf<<<18, 256>>>(sc + S_GLP, 4608);
    // 4. atomic-free segment sums (cp.async staged)
    segsum3_kernel<<<dim3(12, 4, 3), 256, SEG3_SMEM_BYTES>>>(hd1, h1, mask,
                                                             sc + S_PART, sc + S_GLP);
    // 5. all_fv (+ area output)
    finalize2<<<512, 256>>>(sc + S_PART, acnt, sc + S_GLP, sc + S_AF, out + O_ARE);
    // 6. emb = all_fv @ embed_w  [512,256], K=768, split-K 4
    launch_gemm(sc + S_AF, 768, 0, embed_w, EE, 0, sc + S_EM, EE, 0,
                512, EE, 768, 0, 1, 4, P);
    // 7. emb_patches
    embp_kernel<<<4, 256>>>(sc + S_EM, sc + S_EP);
    // 8. comp
    comp_fused<<<4, 256>>>(sc + S_EP, comp_w1, comp_w2, sc + S_CP, out + O_CMP);
    // 9. hist hidden
    launch_gemm(sc + S_EM, EE, 0, hist_w1, EE, 0, sc + S_HH, EE, 0,
                512, EE, EE, 1, 1, 4, P);
    // 10. out_cell_type
    gemmN16<<<16, 256, 32 * EE * sizeof(float)>>>(sc + S_HH, hist_w2, out + O_OCT, EE, 0);
    // 11. branch hidden
    launch_gemm(sc + S_EM, EE, 0, wref_w1, EE, (long long)EE * EE,
                sc + S_HH, EE, (long long)512 * EE, 512, EE, EE, 1, 3, 2, P);
    // 12. rw logits
    launch_gemm(sc + S_HH, EE, (long long)512 * EE, wref_w2, 64, (long long)EE * 64,
                sc + S_RW, 64, (long long)512 * 64, 512, 64, EE, 0, 3, 4, P);
    // 13. softmax rows
    softmax64_kernel<<<3 * 512, 64>>>(sc + S_RW);
    // 14. refw = rw @ ref_orig
    launch_gemm(sc + S_RW, 64, (long long)512 * 64, ref_orig, GG, 0,
                out + O_OE0, GG, 262144LL, 512, GG, 64, 0, 3, 1, P);
    // 15-16. kf/vf
    launch_gemm(out + O_OE0, GG, 262144LL, ca_wk, EE, (long long)GG * EE,
                sc + S_KF, EE, (long long)512 * EE, 512, EE, GG, 0, 3, 2, P);
    launch_gemm(out + O_OE0, GG, 262144LL, ca_wv, EE, (long long)GG * EE,
                sc + S_VF, EE, (long long)512 * EE, 512, EE, GG, 0, 3, 2, P);
    // 17. attention
    attn_kernel<<<dim3(4, 8, 3), 256>>>(sc + S_CP, ca_wq, sc + S_KF, sc + S_VF, sc + S_OB);
    // 18. obwo
    obwo_kernel<<<dim3(4, 1, 3), 512>>>(sc + S_OB, ca_wo, sc + S_OW);
    // 19. out_exprs = relu(refw + tile(obwo))
    addrelu_kernel<<<dim3(512, 1, 3), 512>>>(out + O_OE0, sc + S_OW);
    // 20. genes_h
    launch_gemm(out + O_OE0, GG, 0, genes_w1, EE, 0, out + O_GH, EE, 0,
                512, EE, GG, 1, 1, 4, P);
    // 21. out_cell_type_expr
    gemmN16<<<16, 256, 32 * EE * sizeof(float)>>>(out + O_GH, genes_w2, out + O_OCTE, EE, 0);
}

// round 10
// speedup vs baseline: 1.8134x; 1.0858x over previous
#include <cuda_runtime.h>
#include <stdint.h>
#include <math.h>

#define HW    65536
#define CF    384
#define EE    256
#define GG    512
#define NCC   16

// ---- scratch layout (floats) ----
#define S_PART 0            // segsum partials [3ps][4b][129cell][384ch] = 594432
#define S_GLP  594432       // glob partials [3ps][4b][384] = 4608
#define S_ACNT 599040       // area counts (int) [4][129], padded to 1024
#define S_AF   600064       // allfv  [512][768]
#define S_EM   993280       // emb    [512][256]
#define S_CP   1125376      // comp   [4][16] (pad 64)
#define S_HH   1125440      // hidden [3][512][256]
#define S_RW   1518656      // rw     [3][512][64]
#define S_KF   1616960      // kf     [3][512][256]
#define S_VF   2010176      // vf     [3][512][256]  (must be S_KF + 393216)
#define S_OB   2403392      // ob     [3][4][256]
#define S_OW   2406464      // obwo   [3][4][512] (pad)
#define S_P    2412608      // split-K partials (max 12*131072 = 1572864)
#define SCRATCH_FLOATS (2412608 + 1572864)

__device__ float g_scratch[SCRATCH_FLOATS];

// ---- d_out layout (floats) ----
#define O_OCT  0
#define O_OE0  8192
#define O_OCTE 794624
#define O_GH   802816
#define O_CMP  933888
#define O_ARE  933952

// per-warp smem (floats): acc 32*129=4128, two tile bufs 32*33 each, two id bufs
#define W2_T0  4128
#define W2_T1  5184
#define W2_I0  6240
#define W2_I1  6272
#define W2_SZ  6304
#define SEG3_SMEM_BYTES (8 * W2_SZ * 4)   // 201728

__device__ __forceinline__ uint32_t smem_u32(const void* p)
{
    uint32_t a;
    asm("{ .reg .u64 t; cvta.to.shared.u64 t, %1; cvt.u32.u64 %0, t; }"
        : "=r"(a) : "l"(p));
    return a;
}
__device__ __forceinline__ void cpa4(uint32_t dst, const void* src)
{
    asm volatile("cp.async.ca.shared.global [%0], [%1], 4;" :: "r"(dst), "l"(src));
}
#define CPA_COMMIT() asm volatile("cp.async.commit_group;")
#define CPA_WAIT1()  asm volatile("cp.async.wait_group 1;")
#define CPA_WAIT0()  asm volatile("cp.async.wait_group 0;")

// ============================================================
// Atomic-free segment sum, cp.async-staged, depth-2 ring per warp.
// (unchanged from round 9 — measured 123us, DRAM 41.8%)
// ============================================================
__global__ void __launch_bounds__(256, 1)
segsum3_kernel(const float* __restrict__ hd1,
               const float* __restrict__ h1,
               const int* __restrict__ mask,
               float* __restrict__ partial,
               float* __restrict__ globpart)
{
    extern __shared__ float smem[];
    int cg = blockIdx.x, b = blockIdx.y, ps = blockIdx.z;
    int tid = threadIdx.x, lane = tid & 31, w = tid >> 5;

    for (int i = tid; i < 8 * W2_SZ; i += 256) smem[i] = 0.f;
    __syncthreads();

    const float* base = (cg < 8)
        ? hd1 + (((size_t)b * 256 + cg * 32) << 16)
        : h1  + (((size_t)b * 128 + (cg - 8) * 32) << 16);
    const int* mp = mask + ((size_t)b << 16);

    float* acc  = smem + w * W2_SZ;
    float* tile0 = smem + w * W2_SZ + W2_T0;
    float* tile1 = smem + w * W2_SZ + W2_T1;
    int*   ids0 = (int*)(smem + w * W2_SZ + W2_I0);
    int*   ids1 = (int*)(smem + w * W2_SZ + W2_I1);
    uint32_t tB0 = smem_u32(tile0), tB1 = smem_u32(tile1);
    uint32_t iB0 = smem_u32(ids0),  iB1 = smem_u32(ids1);

    int L = lane * 129;
    int T = lane * 33;
    float tot = 0.f;

    int tb = ps * 683;
    int te = (ps < 2) ? tb + 683 : 2048;
    int t0 = tb + w;
    int cnt = (t0 < te) ? (te - t0 + 7) / 8 : 0;

#define SEG_PREFETCH(tt, TB, IB)                                        \
    do {                                                                \
        const float* cp_ = base + (tt) * 32 + lane;                     \
        uint32_t td_ = (TB) + lane * 4;                                 \
        _Pragma("unroll")                                               \
        for (int c_ = 0; c_ < 32; c_++)                                 \
            cpa4(td_ + c_ * (33 * 4), cp_ + ((size_t)c_ << 16));        \
        cpa4((IB) + lane * 4, mp + (tt) * 32 + lane);                   \
    } while (0)

    if (cnt > 0) { SEG_PREFETCH(t0, tB0, iB0); CPA_COMMIT(); }

    for (int i = 0; i < cnt; i++) {
        int cur = i & 1;
        if (i + 1 < cnt) {
            int tn = t0 + (i + 1) * 8;
            if ((i + 1) & 1) SEG_PREFETCH(tn, tB1, iB1);
            else             SEG_PREFETCH(tn, tB0, iB0);
            CPA_COMMIT();
            CPA_WAIT1();
        } else {
            CPA_WAIT0();
        }
        __syncwarp();
        const float* tile = cur ? tile1 : tile0;
        const int*   ids  = cur ? ids1  : ids0;
#pragma unroll
        for (int p = 0; p < 32; p += 4) {
            int i0 = ids[p], i1 = ids[p + 1], i2 = ids[p + 2], i3 = ids[p + 3];
            float t0v = tile[T + p],     t1v = tile[T + p + 1];
            float t2v = tile[T + p + 2], t3v = tile[T + p + 3];
            tot += (t0v + t1v) + (t2v + t3v);
            bool u1 = (i1 != i0);
            bool u2 = (i2 != i0) && (i2 != i1);
            bool u3 = (i3 != i0) && (i3 != i1) && (i3 != i2);
            if (!u3) { if (i3 == i0) t0v += t3v; else if (i3 == i1) t1v += t3v; else t2v += t3v; }
            if (!u2) { if (i2 == i0) t0v += t2v; else t1v += t2v; }
            if (!u1) t0v += t1v;
            float a0 = acc[L + i0] + t0v;
            float a1 = u1 ? acc[L + i1] + t1v : 0.f;
            float a2 = u2 ? acc[L + i2] + t2v : 0.f;
            float a3 = u3 ? acc[L + i3] + t3v : 0.f;
            acc[L + i0] = a0;
            if (u1) acc[L + i1] = a1;
            if (u2) acc[L + i2] = a2;
            if (u3) acc[L + i3] = a3;
        }
        __syncwarp();
    }
#undef SEG_PREFETCH

    __syncwarp();
    ((float*)ids0)[lane] = tot;
    __syncthreads();

    if (tid < 32) {
        float s = 0.f;
#pragma unroll
        for (int ww = 0; ww < 8; ww++) s += smem[ww * W2_SZ + W2_I0 + tid];
        globpart[(size_t)(ps * 4 + b) * 384 + cg * 32 + tid] = s;
    }

    float* outp = partial + ((size_t)(ps * 4 + b) * 129 * 384) + cg * 32;
    for (int i = tid; i < 129 * 32; i += 256) {
        int cell = i >> 5, ch = i & 31;
        float s = 0.f;
#pragma unroll
        for (int ww = 0; ww < 8; ww++) s += smem[ww * W2_SZ + ch * 129 + cell];
        outp[(size_t)cell * 384 + ch] = s;
    }
}

// ============================================================
__global__ void zero_acnt(int* __restrict__ cnt)
{
    int i = threadIdx.x;
    if (i < 516) cnt[i] = 0;
}

// filler so segsum3 lands on the ncu capture slot (launch #4)
__global__ void zero_buf(float* __restrict__ p, int n)
{
    int i = blockIdx.x * 256 + threadIdx.x;
    if (i < n) p[i] = 0.f;
}

__global__ void hist_kernel(const int* __restrict__ mask, int* __restrict__ cnt)
{
    int b = blockIdx.x, ch = blockIdx.y, tid = threadIdx.x;
    __shared__ int h[129];
    if (tid < 129) h[tid] = 0;
    __syncthreads();
    const int* mp = mask + ((size_t)b << 16) + ch * 4096;
    for (int i = tid; i < 4096; i += 256)
        atomicAdd(&h[mp[i]], 1);
    __syncthreads();
    if (tid < 129 && h[tid]) atomicAdd(&cnt[b * 129 + tid], h[tid]);
}

// ============================================================
__global__ void finalize2(const float* __restrict__ partial,
                          const int* __restrict__ acnt,
                          const float* __restrict__ globpart,
                          float* __restrict__ allfv, float* __restrict__ out_area)
{
    int n = blockIdx.x, tid = threadIdx.x;
    int b = n >> 7, cell = n & 127;
    int a = acnt[b * 129 + cell + 1];
    if (tid == 0) out_area[n] = (float)a;
    float inva = 1.f / fmaxf((float)a, 1.f);
    const size_t PS = (size_t)4 * 129 * 384;
    size_t rp0 = (size_t)b * 129 * 384 + (size_t)(cell + 1) * 384;
    for (int j = tid; j < 768; j += 256) {
        float v;
        if (j < 384) {
            v = (partial[rp0 + j] + partial[rp0 + PS + j] + partial[rp0 + 2 * PS + j]) * inva;
        } else {
            int c = j - 384;
            v = (globpart[(size_t)b * 384 + c] + globpart[(size_t)(4 + b) * 384 + c]
               + globpart[(size_t)(8 + b) * 384 + c]) * (1.f / 65536.f);
        }
        allfv[(size_t)n * 768 + j] = v;
    }
}

// ============================================================
// GEMM: 64x64 tile, BK=16, 4x4 microtile, 256 threads.
// v2: register prefetch of next tile before the FMA block (L2 latency
// overlapped with 256 FFMAs/thread).
// ============================================================
__global__ void gemm64(const float* __restrict__ A, int lda, long long sAz,
                       const float* __restrict__ B, int ldb, long long sBz,
                       float* __restrict__ C, int ldc, long long sCz,
                       int M, int N, int K, int KS, int relu)
{
    int KC = K / KS;
    int br = blockIdx.z / KS, kc = blockIdx.z - br * KS;
    A += (size_t)br * sAz + (size_t)kc * KC;
    B += (size_t)br * sBz + (size_t)kc * KC * ldb;
    if (KS == 1) C += (size_t)br * sCz;
    else         C += (size_t)blockIdx.z * ((size_t)M * ldc);

    __shared__ float As[16][64];
    __shared__ float Bs[16][64];
    int tid = threadIdx.x;
    int tx = tid & 15, ty = tid >> 4;
    int row0 = blockIdx.y * 64, col0 = blockIdx.x * 64;

    int arow = tid >> 2, ak4 = (tid & 3) * 4;
    int brow = tid >> 4, bc4 = (tid & 15) * 4;

    const float* Ap = A + (size_t)(row0 + arow) * lda + ak4;
    const float* Bp = B + (size_t)brow * ldb + col0 + bc4;

    float acc[4][4] = {};
    float4 av = *(const float4*)(Ap);
    float4 bv = *(const float4*)(Bp);
    for (int k0 = 0; k0 < KC; k0 += 16) {
        As[ak4 + 0][arow] = av.x;
        As[ak4 + 1][arow] = av.y;
        As[ak4 + 2][arow] = av.z;
        As[ak4 + 3][arow] = av.w;
        *(float4*)&Bs[brow][bc4] = bv;
        __syncthreads();
        if (k0 + 16 < KC) {
            av = *(const float4*)(Ap + k0 + 16);
            bv = *(const float4*)(Bp + (size_t)(k0 + 16) * ldb);
        }
#pragma unroll
        for (int k = 0; k < 16; k++) {
            float4 a = *(const float4*)&As[k][ty * 4];
            float4 b = *(const float4*)&Bs[k][tx * 4];
            acc[0][0] += a.x * b.x; acc[0][1] += a.x * b.y; acc[0][2] += a.x * b.z; acc[0][3] += a.x * b.w;
            acc[1][0] += a.y * b.x; acc[1][1] += a.y * b.y; acc[1][2] += a.y * b.z; acc[1][3] += a.y * b.w;
            acc[2][0] += a.z * b.x; acc[2][1] += a.z * b.y; acc[2][2] += a.z * b.z; acc[2][3] += a.z * b.w;
            acc[3][0] += a.w * b.x; acc[3][1] += a.w * b.y; acc[3][2] += a.w * b.z; acc[3][3] += a.w * b.w;
        }
        __syncthreads();
    }
#pragma unroll
    for (int i = 0; i < 4; i++) {
        float4 v = make_float4(acc[i][0], acc[i][1], acc[i][2], acc[i][3]);
        if (relu && KS == 1) {
            v.x = fmaxf(v.x, 0.f); v.y = fmaxf(v.y, 0.f);
            v.z = fmaxf(v.z, 0.f); v.w = fmaxf(v.w, 0.f);
        }
        *(float4*)&C[(size_t)(row0 + ty * 4 + i) * ldc + col0 + tx * 4] = v;
    }
}

// ============================================================
// Dual-B GEMM for kf+vf merged: z in 0..11 = mat*6 + br*2 + kc (KS=2).
// A = refw (br-dep), B = wk/wv by mat. Writes partial slice z of P.
// ============================================================
__global__ void gemm64kv(const float* __restrict__ A, int lda, long long sAz,
                         const float* __restrict__ Bk, const float* __restrict__ Bv,
                         int ldb, long long sBz,
                         float* __restrict__ P, int ldc, int M, int N, int K)
{
    int z = blockIdx.z;
    int mat = z / 6, rr = z - mat * 6;
    int br = rr >> 1, kc = rr & 1;
    int KC = K / 2;
    const float* B = (mat ? Bv : Bk) + (size_t)br * sBz + (size_t)kc * KC * ldb;
    A += (size_t)br * sAz + (size_t)kc * KC;
    float* C = P + (size_t)z * ((size_t)M * ldc);

    __shared__ float As[16][64];
    __shared__ float Bs[16][64];
    int tid = threadIdx.x;
    int tx = tid & 15, ty = tid >> 4;
    int row0 = blockIdx.y * 64, col0 = blockIdx.x * 64;

    int arow = tid >> 2, ak4 = (tid & 3) * 4;
    int brow = tid >> 4, bc4 = (tid & 15) * 4;

    const float* Ap = A + (size_t)(row0 + arow) * lda + ak4;
    const float* Bp = B + (size_t)brow * ldb + col0 + bc4;

    float acc[4][4] = {};
    float4 av = *(const float4*)(Ap);
    float4 bv = *(const float4*)(Bp);
    for (int k0 = 0; k0 < KC; k0 += 16) {
        As[ak4 + 0][arow] = av.x;
        As[ak4 + 1][arow] = av.y;
        As[ak4 + 2][arow] = av.z;
        As[ak4 + 3][arow] = av.w;
        *(float4*)&Bs[brow][bc4] = bv;
        __syncthreads();
        if (k0 + 16 < KC) {
            av = *(const float4*)(Ap + k0 + 16);
            bv = *(const float4*)(Bp + (size_t)(k0 + 16) * ldb);
        }
#pragma unroll
        for (int k = 0; k < 16; k++) {
            float4 a = *(const float4*)&As[k][ty * 4];
            float4 b = *(const float4*)&Bs[k][tx * 4];
            acc[0][0] += a.x * b.x; acc[0][1] += a.x * b.y; acc[0][2] += a.x * b.z; acc[0][3] += a.x * b.w;
            acc[1][0] += a.y * b.x; acc[1][1] += a.y * b.y; acc[1][2] += a.y * b.z; acc[1][3] += a.y * b.w;
            acc[2][0] += a.z * b.x; acc[2][1] += a.z * b.y; acc[2][2] += a.z * b.z; acc[2][3] += a.z * b.w;
            acc[3][0] += a.w * b.x; acc[3][1] += a.w * b.y; acc[3][2] += a.w * b.z; acc[3][3] += a.w * b.w;
        }
        __syncthreads();
    }
#pragma unroll
    for (int i = 0; i < 4; i++) {
        float4 v = make_float4(acc[i][0], acc[i][1], acc[i][2], acc[i][3]);
        *(float4*)&C[(size_t)(row0 + ty * 4 + i) * ldc + col0 + tx * 4] = v;
    }
}

__global__ void reducek_kernel(const float* __restrict__ P, float* __restrict__ C,
                               long long sCz, long long slice, int KS, int relu)
{
    int brz = blockIdx.y;
    long long idx = (long long)blockIdx.x * 256 + threadIdx.x;
    const float* p = P + (size_t)brz * KS * slice + idx;
    float s = 0.f;
    for (int j = 0; j < KS; j++) s += p[(size_t)j * slice];
    if (relu) s = fmaxf(s, 0.f);
    C[(size_t)brz * sCz + idx] = s;
}

// ============================================================
__global__ void gemmN16(const float* __restrict__ A, const float* __restrict__ B,
                        float* __restrict__ C, int K, int relu)
{
    extern __shared__ float As[];
    int tid = threadIdx.x;
    int row0 = blockIdx.x * 32;
    for (int i = tid; i < 32 * K; i += 256)
        As[i] = A[(size_t)row0 * K + i];
    __syncthreads();
    int r = tid >> 3, cg = tid & 7;
    int c0 = cg * 2;
    float s0 = 0.f, s1 = 0.f;
    const float* ar = As + r * K;
#pragma unroll 4
    for (int k = 0; k < K; k++) {
        float a = ar[k];
        s0 += a * B[k * 16 + c0];
        s1 += a * B[k * 16 + c0 + 1];
    }
    if (relu) { s0 = fmaxf(s0, 0.f); s1 = fmaxf(s1, 0.f); }
    C[(size_t)(row0 + r) * 16 + c0]     = s0;
    C[(size_t)(row0 + r) * 16 + c0 + 1] = s1;
}

// ============================================================
// fused: embp (mean over 128 cells) + comp = softmax(relu(embp@w1)@w2)
// ============================================================
__global__ void embp_comp_fused(const float* __restrict__ emb,
                                const float* __restrict__ w1, const float* __restrict__ w2,
                                float* __restrict__ comp, float* __restrict__ comp_out)
{
    int b = blockIdx.x, tid = threadIdx.x;
    __shared__ float ep[EE];
    __shared__ float t1[EE];
    __shared__ float t2[NCC];
    float s0 = 0.f;
    for (int i = 0; i < 128; i++)
        s0 += emb[(size_t)(b * 128 + i) * EE + tid];
    ep[tid] = s0 * (1.f / 128.f);
    __syncthreads();
    float s = 0.f;
    for (int c = 0; c < EE; c++)
        s += ep[c] * w1[(size_t)c * EE + tid];
    t1[tid] = fmaxf(s, 0.f);
    __syncthreads();
    if (tid < NCC) {
        float s2 = 0.f;
        for (int j = 0; j < EE; j++)
            s2 += t1[j] * w2[(size_t)j * NCC + tid];
        t2[tid] = s2;
    }
    __syncthreads();
    if (tid == 0) {
        float m = t2[0];
        for (int o = 1; o < NCC; o++) m = fmaxf(m, t2[o]);
        float tot = 0.f;
        float e[NCC];
        for (int o = 0; o < NCC; o++) { e[o] = expf(t2[o] - m); tot += e[o]; }
        float inv = 1.f / tot;
        for (int o = 0; o < NCC; o++) {
            comp[b * NCC + o] = e[o] * inv;
            comp_out[b * NCC + o] = e[o] * inv;
        }
    }
}

// ============================================================
__global__ void softmax64_kernel(float* __restrict__ x)
{
    int r = blockIdx.x, tid = threadIdx.x;
    float* row = x + (size_t)r * 64;
    float v = row[tid];
    __shared__ float sm[4];
    int lane = tid & 31, warp = tid >> 5;
    float m = v;
    for (int off = 16; off; off >>= 1) m = fmaxf(m, __shfl_xor_sync(0xffffffff, m, off));
    if (lane == 0) sm[warp] = m;
    __syncthreads();
    m = fmaxf(sm[0], sm[1]);
    float e = expf(v - m);
    float s = e;
    for (int off = 16; off; off >>= 1) s += __shfl_xor_sync(0xffffffff, s, off);
    if (lane == 0) sm[2 + warp] = s;
    __syncthreads();
    s = sm[2] + sm[3];
    row[tid] = e / s;
}

// ============================================================
__global__ void attn_kernel(const float* __restrict__ comp,
                            const float* __restrict__ ca_wq,
                            const float* __restrict__ kf,
                            const float* __restrict__ vf,
                            float* __restrict__ ob)
{
    int b = blockIdx.x, h = blockIdx.y, br = blockIdx.z;
    int tid = threadIdx.x, lane = tid & 31, warp = tid >> 5;
    const float* wq  = ca_wq + (size_t)br * 16 * EE;
    const float* kfp = kf + (size_t)br * 512 * EE;
    const float* vfp = vf + (size_t)br * 512 * EE;

    __shared__ float q[32];
    __shared__ float sc[512];
    __shared__ float r1[256];
    __shared__ float part[8][32];

    if (tid < 32) {
        float s = 0.f;
        for (int c = 0; c < NCC; c++)
            s += comp[b * NCC + c] * wq[(size_t)c * EE + h * 32 + tid];
        q[tid] = s * 0.17677669529663687f;
    }
    __syncthreads();

    for (int kk = 0; kk < 64; kk++) {
        int kn = warp * 64 + kk;
        float p = q[lane] * kfp[(size_t)kn * EE + h * 32 + lane];
        for (int off = 16; off; off >>= 1) p += __shfl_down_sync(0xffffffff, p, off);
        if (lane == 0) sc[kn] = p;
    }
    __syncthreads();

    float m = fmaxf(sc[tid], sc[tid + 256]);
    r1[tid] = m; __syncthreads();
    for (int s = 128; s > 0; s >>= 1) { if (tid < s) r1[tid] = fmaxf(r1[tid], r1[tid + s]); __syncthreads(); }
    float maxv = r1[0]; __syncthreads();
    float e0 = expf(sc[tid] - maxv), e1 = expf(sc[tid + 256] - maxv);
    sc[tid] = e0; sc[tid + 256] = e1;
    r1[tid] = e0 + e1; __syncthreads();
    for (int s = 128; s > 0; s >>= 1) { if (tid < s) r1[tid] += r1[tid + s]; __syncthreads(); }
    float invs = 1.f / r1[0];

    float a = 0.f;
    for (int kn = warp; kn < 512; kn += 8)
        a += sc[kn] * vfp[(size_t)kn * EE + h * 32 + lane];
    part[warp][lane] = a;
    __syncthreads();
    if (tid < 32) {
        float s = 0.f;
        for (int w = 0; w < 8; w++) s += part[w][tid];
        ob[((size_t)br * 4 + b) * EE + h * 32 + tid] = s * invs;
    }
}

// ============================================================
__global__ void obwo_kernel(const float* __restrict__ ob, const float* __restrict__ ca_wo,
                            float* __restrict__ obwo)
{
    int b = blockIdx.x, br = blockIdx.z, tid = threadIdx.x;
    const float* wo = ca_wo + (size_t)br * EE * GG;
    __shared__ float obs[EE];
    if (tid < EE) obs[tid] = ob[((size_t)br * 4 + b) * EE + tid];
    __syncthreads();
    float s = 0.f;
    for (int c = 0; c < EE; c++)
        s += obs[c] * wo[(size_t)c * GG + tid];
    obwo[((size_t)br * 4 + b) * GG + tid] = s;
}

// ============================================================
__global__ void addrelu_kernel(float* __restrict__ oe_base, const float* __restrict__ obwo)
{
    int n = blockIdx.x, br = blockIdx.z, g = threadIdx.x;
    int b = n >> 7;
    float* oe = oe_base + (size_t)br * 262144;
    float v = oe[(size_t)n * GG + g] + obwo[((size_t)br * 4 + b) * GG + g];
    oe[(size_t)n * GG + g] = fmaxf(v, 0.f);
}

// ============================================================
static inline void launch_gemm(const float* A, int lda, long long sAz,
                               const float* B, int ldb, long long sBz,
                               float* C, int ldc, long long sCz,
                               int M, int N, int K, int relu, int nz, int KS,
                               float* partial)
{
    dim3 grid(N / 64, M / 64, nz * KS);
    if (KS == 1) {
        gemm64<<<grid, 256>>>(A, lda, sAz, B, ldb, sBz, C, ldc, sCz, M, N, K, 1, relu);
    } else {
        gemm64<<<grid, 256>>>(A, lda, sAz, B, ldb, sBz, partial, ldc, 0, M, N, K, KS, 0);
        long long slice = (long long)M * ldc;
        reducek_kernel<<<dim3((unsigned)(slice / 256), nz), 256>>>(partial, C, sCz, slice, KS, relu);
    }
}

extern "C" void kernel_launch(void* const* d_in, const int* in_sizes, int n_in,
                              void* d_out, int out_size)
{
    (void)in_sizes; (void)n_in; (void)out_size;
    const float* hd1      = (const float*)d_in[0];
    const float* h1       = (const float*)d_in[1];
    const float* ref_orig = (const float*)d_in[2];
    const float* embed_w  = (const float*)d_in[3];
    const float* comp_w1  = (const float*)d_in[4];
    const float* comp_w2  = (const float*)d_in[5];
    const float* hist_w1  = (const float*)d_in[6];
    const float* hist_w2  = (const float*)d_in[7];
    const float* genes_w1 = (const float*)d_in[8];
    const float* genes_w2 = (const float*)d_in[9];
    const float* wref_w1  = (const float*)d_in[10];
    const float* wref_w2  = (const float*)d_in[11];
    const float* ca_wq    = (const float*)d_in[12];
    const float* ca_wk    = (const float*)d_in[13];
    const float* ca_wv    = (const float*)d_in[14];
    const float* ca_wo    = (const float*)d_in[15];
    const int*   mask     = (const int*)d_in[16];
    float* out = (float*)d_out;

    float* sc = nullptr;
    cudaGetSymbolAddress((void**)&sc, g_scratch);
    float* P = sc + S_P;
    int* acnt = (int*)(sc + S_ACNT);

    cudaFuncSetAttribute(segsum3_kernel,
                         cudaFuncAttributeMaxDynamicSharedMemorySize, SEG3_SMEM_BYTES);

    // 1-2. area histogram (int, deterministic)
    zero_acnt<<<1, 516>>>(acnt);
    hist_kernel<<<dim3(4, 16), 256>>>(mask, acnt);
    // 3. filler (keeps segsum3 on the ncu capture slot)
    zero_buf<<<18, 256>>>(sc + S_GLP, 4608);
    // 4. atomic-free segment sums (cp.async staged)
    segsum3_kernel<<<dim3(12, 4, 3), 256, SEG3_SMEM_BYTES>>>(hd1, h1, mask,
                                                             sc + S_PART, sc + S_GLP);
    // 5. all_fv (+ area output)
    finalize2<<<512, 256>>>(sc + S_PART, acnt, sc + S_GLP, sc + S_AF, out + O_ARE);
    // 6. emb = all_fv @ embed_w  [512,256], K=768, split-K 4
    launch_gemm(sc + S_AF, 768, 0, embed_w, EE, 0, sc + S_EM, EE, 0,
                512, EE, 768, 0, 1, 4, P);
    // 7. embp + comp fused
    embp_comp_fused<<<4, 256>>>(sc + S_EM, comp_w1, comp_w2, sc + S_CP, out + O_CMP);
    // 8. hist hidden
    launch_gemm(sc + S_EM, EE, 0, hist_w1, EE, 0, sc + S_HH, EE, 0,
                512, EE, EE, 1, 1, 4, P);
    // 9. out_cell_type
    gemmN16<<<16, 256, 32 * EE * sizeof(float)>>>(sc + S_HH, hist_w2, out + O_OCT, EE, 0);
    // 10. branch hidden
    launch_gemm(sc + S_EM, EE, 0, wref_w1, EE, (long long)EE * EE,
                sc + S_HH, EE, (long long)512 * EE, 512, EE, EE, 1, 3, 2, P);
    // 11. rw logits
    launch_gemm(sc + S_HH, EE, (long long)512 * EE, wref_w2, 64, (long long)EE * 64,
                sc + S_RW, 64, (long long)512 * 64, 512, 64, EE, 0, 3, 4, P);
    // 12. softmax rows
    softmax64_kernel<<<3 * 512, 64>>>(sc + S_RW);
    // 13. refw = rw @ ref_orig
    launch_gemm(sc + S_RW, 64, (long long)512 * 64, ref_orig, GG, 0,
                out + O_OE0, GG, 262144LL, 512, GG, 64, 0, 3, 1, P);
    // 14. kf+vf merged (z=12, KS=2) -> P, reduce into S_KF/S_VF contiguously
    gemm64kv<<<dim3(EE / 64, 512 / 64, 12), 256>>>(out + O_OE0, GG, 262144LL,
                                                   ca_wk, ca_wv, EE, (long long)GG * EE,
                                                   P, EE, 512, EE, GG);
    reducek_kernel<<<dim3(512, 6), 256>>>(P, sc + S_KF, (long long)512 * EE,
                                          (long long)512 * EE, 2, 0);
    // 15. attention
    attn_kernel<<<dim3(4, 8, 3), 256>>>(sc + S_CP, ca_wq, sc + S_KF, sc + S_VF, sc + S_OB);
    // 16. obwo
    obwo_kernel<<<dim3(4, 1, 3), 512>>>(sc + S_OB, ca_wo, sc + S_OW);
    // 17. out_exprs = relu(refw + tile(obwo))
    addrelu_kernel<<<dim3(512, 1, 3), 512>>>(out + O_OE0, sc + S_OW);
    // 18. genes_h
    launch_gemm(out + O_OE0, GG, 0, genes_w1, EE, 0, out + O_GH, EE, 0,
                512, EE, GG, 1, 1, 4, P);
    // 19. out_cell_type_expr
    gemmN16<<<16, 256, 32 * EE * sizeof(float)>>>(out + O_GH, genes_w2, out + O_OCTE, EE, 0);
}

// round 11
// speedup vs baseline: 1.8359x; 1.0124x over previous
#include <cuda_runtime.h>
#include <stdint.h>
#include <math.h>

#define HW    65536
#define CF    384
#define EE    256
#define GG    512
#define NCC   16

// ---- scratch layout (floats) ----
#define S_PART 0            // segsum partials [3ps][4b][129cell][384ch] = 594432
#define S_GLP  594432       // glob partials [3ps][4b][384] = 4608
#define S_ACNT 599040       // area counts (int) [4][129], padded to 1024
#define S_AF   600064       // allfv  [512][768]
#define S_EM   993280       // emb    [512][256]
#define S_CP   1125376      // comp   [4][16] (pad 64)
#define S_HH4  1125440      // hidden [4][512][256]  (slice0=hist, 1..3=branches)
#define S_RW   1649728      // rw     [3][512][64]
#define S_KF   1748032      // kf     [3][512][256]
#define S_VF   2141248      // vf     [3][512][256]  (= S_KF + 393216)
#define S_OB   2534464      // ob     [3][4][256]
#define S_OW   2537536      // obwo   [3][4][512] (pad)
#define S_P    2543680      // split-K partials (16*131072 = 2097152)
#define SCRATCH_FLOATS (2543680 + 2097152)

__device__ float g_scratch[SCRATCH_FLOATS];

// ---- d_out layout (floats) ----
#define O_OCT  0
#define O_OE0  8192
#define O_OCTE 794624
#define O_GH   802816
#define O_CMP  933888
#define O_ARE  933952

// per-warp smem (floats): acc 32*129=4128, two tile bufs 32*33 each, two id bufs
#define W2_T0  4128
#define W2_T1  5184
#define W2_I0  6240
#define W2_I1  6272
#define W2_SZ  6304
#define SEG3_SMEM_BYTES (8 * W2_SZ * 4)   // 201728

__device__ __forceinline__ uint32_t smem_u32(const void* p)
{
    uint32_t a;
    asm("{ .reg .u64 t; cvta.to.shared.u64 t, %1; cvt.u32.u64 %0, t; }"
        : "=r"(a) : "l"(p));
    return a;
}
__device__ __forceinline__ void cpa4(uint32_t dst, const void* src)
{
    asm volatile("cp.async.ca.shared.global [%0], [%1], 4;" :: "r"(dst), "l"(src));
}
#define CPA_COMMIT() asm volatile("cp.async.commit_group;")
#define CPA_WAIT1()  asm volatile("cp.async.wait_group 1;")
#define CPA_WAIT0()  asm volatile("cp.async.wait_group 0;")

// ============================================================
// Atomic-free segment sum, cp.async-staged, depth-2 ring per warp.
// (unchanged — measured 124us, DRAM-bound at 3.3TB/s)
// ============================================================
__global__ void __launch_bounds__(256, 1)
segsum3_kernel(const float* __restrict__ hd1,
               const float* __restrict__ h1,
               const int* __restrict__ mask,
               float* __restrict__ partial,
               float* __restrict__ globpart)
{
    extern __shared__ float smem[];
    int cg = blockIdx.x, b = blockIdx.y, ps = blockIdx.z;
    int tid = threadIdx.x, lane = tid & 31, w = tid >> 5;

    for (int i = tid; i < 8 * W2_SZ; i += 256) smem[i] = 0.f;
    __syncthreads();

    const float* base = (cg < 8)
        ? hd1 + (((size_t)b * 256 + cg * 32) << 16)
        : h1  + (((size_t)b * 128 + (cg - 8) * 32) << 16);
    const int* mp = mask + ((size_t)b << 16);

    float* acc  = smem + w * W2_SZ;
    float* tile0 = smem + w * W2_SZ + W2_T0;
    float* tile1 = smem + w * W2_SZ + W2_T1;
    int*   ids0 = (int*)(smem + w * W2_SZ + W2_I0);
    int*   ids1 = (int*)(smem + w * W2_SZ + W2_I1);
    uint32_t tB0 = smem_u32(tile0), tB1 = smem_u32(tile1);
    uint32_t iB0 = smem_u32(ids0),  iB1 = smem_u32(ids1);

    int L = lane * 129;
    int T = lane * 33;
    float tot = 0.f;

    int tb = ps * 683;
    int te = (ps < 2) ? tb + 683 : 2048;
    int t0 = tb + w;
    int cnt = (t0 < te) ? (te - t0 + 7) / 8 : 0;

#define SEG_PREFETCH(tt, TB, IB)                                        \
    do {                                                                \
        const float* cp_ = base + (tt) * 32 + lane;                     \
        uint32_t td_ = (TB) + lane * 4;                                 \
        _Pragma("unroll")                                               \
        for (int c_ = 0; c_ < 32; c_++)                                 \
            cpa4(td_ + c_ * (33 * 4), cp_ + ((size_t)c_ << 16));        \
        cpa4((IB) + lane * 4, mp + (tt) * 32 + lane);                   \
    } while (0)

    if (cnt > 0) { SEG_PREFETCH(t0, tB0, iB0); CPA_COMMIT(); }

    for (int i = 0; i < cnt; i++) {
        int cur = i & 1;
        if (i + 1 < cnt) {
            int tn = t0 + (i + 1) * 8;
            if ((i + 1) & 1) SEG_PREFETCH(tn, tB1, iB1);
            else             SEG_PREFETCH(tn, tB0, iB0);
            CPA_COMMIT();
            CPA_WAIT1();
        } else {
            CPA_WAIT0();
        }
        __syncwarp();
        const float* tile = cur ? tile1 : tile0;
        const int*   ids  = cur ? ids1  : ids0;
#pragma unroll
        for (int p = 0; p < 32; p += 4) {
            int i0 = ids[p], i1 = ids[p + 1], i2 = ids[p + 2], i3 = ids[p + 3];
            float t0v = tile[T + p],     t1v = tile[T + p + 1];
            float t2v = tile[T + p + 2], t3v = tile[T + p + 3];
            tot += (t0v + t1v) + (t2v + t3v);
            bool u1 = (i1 != i0);
            bool u2 = (i2 != i0) && (i2 != i1);
            bool u3 = (i3 != i0) && (i3 != i1) && (i3 != i2);
            if (!u3) { if (i3 == i0) t0v += t3v; else if (i3 == i1) t1v += t3v; else t2v += t3v; }
            if (!u2) { if (i2 == i0) t0v += t2v; else t1v += t2v; }
            if (!u1) t0v += t1v;
            float a0 = acc[L + i0] + t0v;
            float a1 = u1 ? acc[L + i1] + t1v : 0.f;
            float a2 = u2 ? acc[L + i2] + t2v : 0.f;
            float a3 = u3 ? acc[L + i3] + t3v : 0.f;
            acc[L + i0] = a0;
            if (u1) acc[L + i1] = a1;
            if (u2) acc[L + i2] = a2;
            if (u3) acc[L + i3] = a3;
        }
        __syncwarp();
    }
#undef SEG_PREFETCH

    __syncwarp();
    ((float*)ids0)[lane] = tot;
    __syncthreads();

    if (tid < 32) {
        float s = 0.f;
#pragma unroll
        for (int ww = 0; ww < 8; ww++) s += smem[ww * W2_SZ + W2_I0 + tid];
        globpart[(size_t)(ps * 4 + b) * 384 + cg * 32 + tid] = s;
    }

    float* outp = partial + ((size_t)(ps * 4 + b) * 129 * 384) + cg * 32;
    for (int i = tid; i < 129 * 32; i += 256) {
        int cell = i >> 5, ch = i & 31;
        float s = 0.f;
#pragma unroll
        for (int ww = 0; ww < 8; ww++) s += smem[ww * W2_SZ + ch * 129 + cell];
        outp[(size_t)cell * 384 + ch] = s;
    }
}

// ============================================================
__global__ void zero_acnt(int* __restrict__ cnt)
{
    int i = threadIdx.x;
    if (i < 516) cnt[i] = 0;
}

__global__ void zero_buf(float* __restrict__ p, int n)
{
    int i = blockIdx.x * 256 + threadIdx.x;
    if (i < n) p[i] = 0.f;
}

__global__ void hist_kernel(const int* __restrict__ mask, int* __restrict__ cnt)
{
    int b = blockIdx.x, ch = blockIdx.y, tid = threadIdx.x;
    __shared__ int h[129];
    if (tid < 129) h[tid] = 0;
    __syncthreads();
    const int* mp = mask + ((size_t)b << 16) + ch * 4096;
    for (int i = tid; i < 4096; i += 256)
        atomicAdd(&h[mp[i]], 1);
    __syncthreads();
    if (tid < 129 && h[tid]) atomicAdd(&cnt[b * 129 + tid], h[tid]);
}

// ============================================================
__global__ void finalize2(const float* __restrict__ partial,
                          const int* __restrict__ acnt,
                          const float* __restrict__ globpart,
                          float* __restrict__ allfv, float* __restrict__ out_area)
{
    int n = blockIdx.x, tid = threadIdx.x;
    int b = n >> 7, cell = n & 127;
    int a = acnt[b * 129 + cell + 1];
    if (tid == 0) out_area[n] = (float)a;
    float inva = 1.f / fmaxf((float)a, 1.f);
    const size_t PS = (size_t)4 * 129 * 384;
    size_t rp0 = (size_t)b * 129 * 384 + (size_t)(cell + 1) * 384;
    for (int j = tid; j < 768; j += 256) {
        float v;
        if (j < 384) {
            v = (partial[rp0 + j] + partial[rp0 + PS + j] + partial[rp0 + 2 * PS + j]) * inva;
        } else {
            int c = j - 384;
            v = (globpart[(size_t)b * 384 + c] + globpart[(size_t)(4 + b) * 384 + c]
               + globpart[(size_t)(8 + b) * 384 + c]) * (1.f / 65536.f);
        }
        allfv[(size_t)n * 768 + j] = v;
    }
}

// ============================================================
// GEMM: 64x64 tile, BK=16, 4x4 microtile, prefetch pipeline.
// ============================================================
__global__ void gemm64(const float* __restrict__ A, int lda, long long sAz,
                       const float* __restrict__ B, int ldb, long long sBz,
                       float* __restrict__ C, int ldc, long long sCz,
                       int M, int N, int K, int KS, int relu)
{
    int KC = K / KS;
    int br = blockIdx.z / KS, kc = blockIdx.z - br * KS;
    A += (size_t)br * sAz + (size_t)kc * KC;
    B += (size_t)br * sBz + (size_t)kc * KC * ldb;
    if (KS == 1) C += (size_t)br * sCz;
    else         C += (size_t)blockIdx.z * ((size_t)M * ldc);

    __shared__ float As[16][64];
    __shared__ float Bs[16][64];
    int tid = threadIdx.x;
    int tx = tid & 15, ty = tid >> 4;
    int row0 = blockIdx.y * 64, col0 = blockIdx.x * 64;

    int arow = tid >> 2, ak4 = (tid & 3) * 4;
    int brow = tid >> 4, bc4 = (tid & 15) * 4;

    const float* Ap = A + (size_t)(row0 + arow) * lda + ak4;
    const float* Bp = B + (size_t)brow * ldb + col0 + bc4;

    float acc[4][4] = {};
    float4 av = *(const float4*)(Ap);
    float4 bv = *(const float4*)(Bp);
    for (int k0 = 0; k0 < KC; k0 += 16) {
        As[ak4 + 0][arow] = av.x;
        As[ak4 + 1][arow] = av.y;
        As[ak4 + 2][arow] = av.z;
        As[ak4 + 3][arow] = av.w;
        *(float4*)&Bs[brow][bc4] = bv;
        __syncthreads();
        if (k0 + 16 < KC) {
            av = *(const float4*)(Ap + k0 + 16);
            bv = *(const float4*)(Bp + (size_t)(k0 + 16) * ldb);
        }
#pragma unroll
        for (int k = 0; k < 16; k++) {
            float4 a = *(const float4*)&As[k][ty * 4];
            float4 b = *(const float4*)&Bs[k][tx * 4];
            acc[0][0] += a.x * b.x; acc[0][1] += a.x * b.y; acc[0][2] += a.x * b.z; acc[0][3] += a.x * b.w;
            acc[1][0] += a.y * b.x; acc[1][1] += a.y * b.y; acc[1][2] += a.y * b.z; acc[1][3] += a.y * b.w;
            acc[2][0] += a.z * b.x; acc[2][1] += a.z * b.y; acc[2][2] += a.z * b.z; acc[2][3] += a.z * b.w;
            acc[3][0] += a.w * b.x; acc[3][1] += a.w * b.y; acc[3][2] += a.w * b.z; acc[3][3] += a.w * b.w;
        }
        __syncthreads();
    }
#pragma unroll
    for (int i = 0; i < 4; i++) {
        float4 v = make_float4(acc[i][0], acc[i][1], acc[i][2], acc[i][3]);
        if (relu && KS == 1) {
            v.x = fmaxf(v.x, 0.f); v.y = fmaxf(v.y, 0.f);
            v.z = fmaxf(v.z, 0.f); v.w = fmaxf(v.w, 0.f);
        }
        *(float4*)&C[(size_t)(row0 + ty * 4 + i) * ldc + col0 + tx * 4] = v;
    }
}

// ============================================================
// Hidden fused GEMM: zz=0 -> B=hist_w1, zz=1..3 -> wref_w1[zz-1].
// A = emb for all. z = zz*KS + kc. Writes partial slice z.
// ============================================================
__global__ void gemm64h(const float* __restrict__ A, int lda,
                        const float* __restrict__ Bh, const float* __restrict__ Bw,
                        int ldb, long long sBz,
                        float* __restrict__ P, int ldc, int M, int N, int K, int KS)
{
    int z = blockIdx.z;
    int zz = z / KS, kc = z - zz * KS;
    int KC = K / KS;
    const float* B = (zz == 0 ? Bh : Bw + (size_t)(zz - 1) * sBz) + (size_t)kc * KC * ldb;
    const float* Ab = A + (size_t)kc * KC;
    float* C = P + (size_t)z * ((size_t)M * ldc);

    __shared__ float As[16][64];
    __shared__ float Bs[16][64];
    int tid = threadIdx.x;
    int tx = tid & 15, ty = tid >> 4;
    int row0 = blockIdx.y * 64, col0 = blockIdx.x * 64;

    int arow = tid >> 2, ak4 = (tid & 3) * 4;
    int brow = tid >> 4, bc4 = (tid & 15) * 4;

    const float* Ap = Ab + (size_t)(row0 + arow) * lda + ak4;
    const float* Bp = B + (size_t)brow * ldb + col0 + bc4;

    float acc[4][4] = {};
    float4 av = *(const float4*)(Ap);
    float4 bv = *(const float4*)(Bp);
    for (int k0 = 0; k0 < KC; k0 += 16) {
        As[ak4 + 0][arow] = av.x;
        As[ak4 + 1][arow] = av.y;
        As[ak4 + 2][arow] = av.z;
        As[ak4 + 3][arow] = av.w;
        *(float4*)&Bs[brow][bc4] = bv;
        __syncthreads();
        if (k0 + 16 < KC) {
            av = *(const float4*)(Ap + k0 + 16);
            bv = *(const float4*)(Bp + (size_t)(k0 + 16) * ldb);
        }
#pragma unroll
        for (int k = 0; k < 16; k++) {
            float4 a = *(const float4*)&As[k][ty * 4];
            float4 b = *(const float4*)&Bs[k][tx * 4];
            acc[0][0] += a.x * b.x; acc[0][1] += a.x * b.y; acc[0][2] += a.x * b.z; acc[0][3] += a.x * b.w;
            acc[1][0] += a.y * b.x; acc[1][1] += a.y * b.y; acc[1][2] += a.y * b.z; acc[1][3] += a.y * b.w;
            acc[2][0] += a.z * b.x; acc[2][1] += a.z * b.y; acc[2][2] += a.z * b.z; acc[2][3] += a.z * b.w;
            acc[3][0] += a.w * b.x; acc[3][1] += a.w * b.y; acc[3][2] += a.w * b.z; acc[3][3] += a.w * b.w;
        }
        __syncthreads();
    }
#pragma unroll
    for (int i = 0; i < 4; i++) {
        float4 v = make_float4(acc[i][0], acc[i][1], acc[i][2], acc[i][3]);
        *(float4*)&C[(size_t)(row0 + ty * 4 + i) * ldc + col0 + tx * 4] = v;
    }
}

// ============================================================
// Dual-B GEMM for kf+vf: z = mat*6 + br*2 + kc  (KS=2).
// ============================================================
__global__ void gemm64kv(const float* __restrict__ A, int lda, long long sAz,
                         const float* __restrict__ Bk, const float* __restrict__ Bv,
                         int ldb, long long sBz,
                         float* __restrict__ P, int ldc, int M, int N, int K)
{
    int z = blockIdx.z;
    int mat = z / 6, rr = z - mat * 6;
    int br = rr >> 1, kc = rr & 1;
    int KC = K / 2;
    const float* B = (mat ? Bv : Bk) + (size_t)br * sBz + (size_t)kc * KC * ldb;
    A += (size_t)br * sAz + (size_t)kc * KC;
    float* C = P + (size_t)z * ((size_t)M * ldc);

    __shared__ float As[16][64];
    __shared__ float Bs[16][64];
    int tid = threadIdx.x;
    int tx = tid & 15, ty = tid >> 4;
    int row0 = blockIdx.y * 64, col0 = blockIdx.x * 64;

    int arow = tid >> 2, ak4 = (tid & 3) * 4;
    int brow = tid >> 4, bc4 = (tid & 15) * 4;

    const float* Ap = A + (size_t)(row0 + arow) * lda + ak4;
    const float* Bp = B + (size_t)brow * ldb + col0 + bc4;

    float acc[4][4] = {};
    float4 av = *(const float4*)(Ap);
    float4 bv = *(const float4*)(Bp);
    for (int k0 = 0; k0 < KC; k0 += 16) {
        As[ak4 + 0][arow] = av.x;
        As[ak4 + 1][arow] = av.y;
        As[ak4 + 2][arow] = av.z;
        As[ak4 + 3][arow] = av.w;
        *(float4*)&Bs[brow][bc4] = bv;
        __syncthreads();
        if (k0 + 16 < KC) {
            av = *(const float4*)(Ap + k0 + 16);
            bv = *(const float4*)(Bp + (size_t)(k0 + 16) * ldb);
        }
#pragma unroll
        for (int k = 0; k < 16; k++) {
            float4 a = *(const float4*)&As[k][ty * 4];
            float4 b = *(const float4*)&Bs[k][tx * 4];
            acc[0][0] += a.x * b.x; acc[0][1] += a.x * b.y; acc[0][2] += a.x * b.z; acc[0][3] += a.x * b.w;
            acc[1][0] += a.y * b.x; acc[1][1] += a.y * b.y; acc[1][2] += a.y * b.z; acc[1][3] += a.y * b.w;
            acc[2][0] += a.z * b.x; acc[2][1] += a.z * b.y; acc[2][2] += a.z * b.z; acc[2][3] += a.z * b.w;
            acc[3][0] += a.w * b.x; acc[3][1] += a.w * b.y; acc[3][2] += a.w * b.z; acc[3][3] += a.w * b.w;
        }
        __syncthreads();
    }
#pragma unroll
    for (int i = 0; i < 4; i++) {
        float4 v = make_float4(acc[i][0], acc[i][1], acc[i][2], acc[i][3]);
        *(float4*)&C[(size_t)(row0 + ty * 4 + i) * ldc + col0 + tx * 4] = v;
    }
}

__global__ void reducek_kernel(const float* __restrict__ P, float* __restrict__ C,
                               long long sCz, long long slice, int KS, int relu)
{
    int brz = blockIdx.y;
    long long idx = (long long)blockIdx.x * 256 + threadIdx.x;
    const float* p = P + (size_t)brz * KS * slice + idx;
    float s = 0.f;
    for (int j = 0; j < KS; j++) s += p[(size_t)j * slice];
    if (relu) s = fmaxf(s, 0.f);
    C[(size_t)brz * sCz + idx] = s;
}

// ============================================================
// Fused split-K(8) reduce + row-softmax for rw logits.
// P slices: [br][8][512][64]. Block = 256 thr = 4 rows of 64.
// ============================================================
__global__ void reduce_softmax64(const float* __restrict__ P, float* __restrict__ rw)
{
    int row = blockIdx.x * 4 + (threadIdx.x >> 6);
    int col = threadIdx.x & 63;
    int br = row >> 9, lr = row & 511;
    long long idx = (long long)lr * 64 + col;
    const float* p = P + (size_t)br * 8 * 32768 + idx;
    float s = 0.f;
#pragma unroll
    for (int j = 0; j < 8; j++) s += p[(size_t)j * 32768];

    int lane = threadIdx.x & 31, half = (threadIdx.x >> 5) & 1, r4 = threadIdx.x >> 6;
    __shared__ float mm[4][2];
    __shared__ float ss[4][2];
    float m = s;
    for (int o = 16; o; o >>= 1) m = fmaxf(m, __shfl_xor_sync(0xffffffffu, m, o));
    if (lane == 0) mm[r4][half] = m;
    __syncthreads();
    m = fmaxf(mm[r4][0], mm[r4][1]);
    float e = expf(s - m);
    float t = e;
    for (int o = 16; o; o >>= 1) t += __shfl_xor_sync(0xffffffffu, t, o);
    if (lane == 0) ss[r4][half] = t;
    __syncthreads();
    t = ss[r4][0] + ss[r4][1];
    rw[(size_t)row * 64 + col] = e / t;
}

// ============================================================
__global__ void gemmN16(const float* __restrict__ A, const float* __restrict__ B,
                        float* __restrict__ C, int K, int relu)
{
    extern __shared__ float As[];
    int tid = threadIdx.x;
    int row0 = blockIdx.x * 32;
    for (int i = tid; i < 32 * K; i += 256)
        As[i] = A[(size_t)row0 * K + i];
    __syncthreads();
    int r = tid >> 3, cg = tid & 7;
    int c0 = cg * 2;
    float s0 = 0.f, s1 = 0.f;
    const float* ar = As + r * K;
#pragma unroll 4
    for (int k = 0; k < K; k++) {
        float a = ar[k];
        s0 += a * B[k * 16 + c0];
        s1 += a * B[k * 16 + c0 + 1];
    }
    if (relu) { s0 = fmaxf(s0, 0.f); s1 = fmaxf(s1, 0.f); }
    C[(size_t)(row0 + r) * 16 + c0]     = s0;
    C[(size_t)(row0 + r) * 16 + c0 + 1] = s1;
}

// ============================================================
__global__ void embp_comp_fused(const float* __restrict__ emb,
                                const float* __restrict__ w1, const float* __restrict__ w2,
                                float* __restrict__ comp, float* __restrict__ comp_out)
{
    int b = blockIdx.x, tid = threadIdx.x;
    __shared__ float ep[EE];
    __shared__ float t1[EE];
    __shared__ float t2[NCC];
    float s0 = 0.f;
    for (int i = 0; i < 128; i++)
        s0 += emb[(size_t)(b * 128 + i) * EE + tid];
    ep[tid] = s0 * (1.f / 128.f);
    __syncthreads();
    float s = 0.f;
    for (int c = 0; c < EE; c++)
        s += ep[c] * w1[(size_t)c * EE + tid];
    t1[tid] = fmaxf(s, 0.f);
    __syncthreads();
    if (tid < NCC) {
        float s2 = 0.f;
        for (int j = 0; j < EE; j++)
            s2 += t1[j] * w2[(size_t)j * NCC + tid];
        t2[tid] = s2;
    }
    __syncthreads();
    if (tid == 0) {
        float m = t2[0];
        for (int o = 1; o < NCC; o++) m = fmaxf(m, t2[o]);
        float tot = 0.f;
        float e[NCC];
        for (int o = 0; o < NCC; o++) { e[o] = expf(t2[o] - m); tot += e[o]; }
        float inv = 1.f / tot;
        for (int o = 0; o < NCC; o++) {
            comp[b * NCC + o] = e[o] * inv;
            comp_out[b * NCC + o] = e[o] * inv;
        }
    }
}

// ============================================================
__global__ void attn_kernel(const float* __restrict__ comp,
                            const float* __restrict__ ca_wq,
                            const float* __restrict__ kf,
                            const float* __restrict__ vf,
                            float* __restrict__ ob)
{
    int b = blockIdx.x, h = blockIdx.y, br = blockIdx.z;
    int tid = threadIdx.x, lane = tid & 31, warp = tid >> 5;
    const float* wq  = ca_wq + (size_t)br * 16 * EE;
    const float* kfp = kf + (size_t)br * 512 * EE;
    const float* vfp = vf + (size_t)br * 512 * EE;

    __shared__ float q[32];
    __shared__ float sc[512];
    __shared__ float r1[256];
    __shared__ float part[8][32];

    if (tid < 32) {
        float s = 0.f;
        for (int c = 0; c < NCC; c++)
            s += comp[b * NCC + c] * wq[(size_t)c * EE + h * 32 + tid];
        q[tid] = s * 0.17677669529663687f;
    }
    __syncthreads();

    for (int kk = 0; kk < 64; kk++) {
        int kn = warp * 64 + kk;
        float p = q[lane] * kfp[(size_t)kn * EE + h * 32 + lane];
        for (int off = 16; off; off >>= 1) p += __shfl_down_sync(0xffffffff, p, off);
        if (lane == 0) sc[kn] = p;
    }
    __syncthreads();

    float m = fmaxf(sc[tid], sc[tid + 256]);
    r1[tid] = m; __syncthreads();
    for (int s = 128; s > 0; s >>= 1) { if (tid < s) r1[tid] = fmaxf(r1[tid], r1[tid + s]); __syncthreads(); }
    float maxv = r1[0]; __syncthreads();
    float e0 = expf(sc[tid] - maxv), e1 = expf(sc[tid + 256] - maxv);
    sc[tid] = e0; sc[tid + 256] = e1;
    r1[tid] = e0 + e1; __syncthreads();
    for (int s = 128; s > 0; s >>= 1) { if (tid < s) r1[tid] += r1[tid + s]; __syncthreads(); }
    float invs = 1.f / r1[0];

    float a = 0.f;
    for (int kn = warp; kn < 512; kn += 8)
        a += sc[kn] * vfp[(size_t)kn * EE + h * 32 + lane];
    part[warp][lane] = a;
    __syncthreads();
    if (tid < 32) {
        float s = 0.f;
        for (int w = 0; w < 8; w++) s += part[w][tid];
        ob[((size_t)br * 4 + b) * EE + h * 32 + tid] = s * invs;
    }
}

// ============================================================
__global__ void obwo_kernel(const float* __restrict__ ob, const float* __restrict__ ca_wo,
                            float* __restrict__ obwo)
{
    int b = blockIdx.x, br = blockIdx.z, tid = threadIdx.x;
    const float* wo = ca_wo + (size_t)br * EE * GG;
    __shared__ float obs[EE];
    if (tid < EE) obs[tid] = ob[((size_t)br * 4 + b) * EE + tid];
    __syncthreads();
    float s = 0.f;
    for (int c = 0; c < EE; c++)
        s += obs[c] * wo[(size_t)c * GG + tid];
    obwo[((size_t)br * 4 + b) * GG + tid] = s;
}

// ============================================================
__global__ void addrelu_kernel(float* __restrict__ oe_base, const float* __restrict__ obwo)
{
    int n = blockIdx.x, br = blockIdx.z, g = threadIdx.x;
    int b = n >> 7;
    float* oe = oe_base + (size_t)br * 262144;
    float v = oe[(size_t)n * GG + g] + obwo[((size_t)br * 4 + b) * GG + g];
    oe[(size_t)n * GG + g] = fmaxf(v, 0.f);
}

// ============================================================
static inline void launch_gemm(const float* A, int lda, long long sAz,
                               const float* B, int ldb, long long sBz,
                               float* C, int ldc, long long sCz,
                               int M, int N, int K, int relu, int nz, int KS,
                               float* partial)
{
    dim3 grid(N / 64, M / 64, nz * KS);
    if (KS == 1) {
        gemm64<<<grid, 256>>>(A, lda, sAz, B, ldb, sBz, C, ldc, sCz, M, N, K, 1, relu);
    } else {
        gemm64<<<grid, 256>>>(A, lda, sAz, B, ldb, sBz, partial, ldc, 0, M, N, K, KS, 0);
        long long slice = (long long)M * ldc;
        reducek_kernel<<<dim3((unsigned)(slice / 256), nz), 256>>>(partial, C, sCz, slice, KS, relu);
    }
}

extern "C" void kernel_launch(void* const* d_in, const int* in_sizes, int n_in,
                              void* d_out, int out_size)
{
    (void)in_sizes; (void)n_in; (void)out_size;
    const float* hd1      = (const float*)d_in[0];
    const float* h1       = (const float*)d_in[1];
    const float* ref_orig = (const float*)d_in[2];
    const float* embed_w  = (const float*)d_in[3];
    const float* comp_w1  = (const float*)d_in[4];
    const float* comp_w2  = (const float*)d_in[5];
    const float* hist_w1  = (const float*)d_in[6];
    const float* hist_w2  = (const float*)d_in[7];
    const float* genes_w1 = (const float*)d_in[8];
    const float* genes_w2 = (const float*)d_in[9];
    const float* wref_w1  = (const float*)d_in[10];
    const float* wref_w2  = (const float*)d_in[11];
    const float* ca_wq    = (const float*)d_in[12];
    const float* ca_wk    = (const float*)d_in[13];
    const float* ca_wv    = (const float*)d_in[14];
    const float* ca_wo    = (const float*)d_in[15];
    const int*   mask     = (const int*)d_in[16];
    float* out = (float*)d_out;

    float* sc = nullptr;
    cudaGetSymbolAddress((void**)&sc, g_scratch);
    float* P = sc + S_P;
    int* acnt = (int*)(sc + S_ACNT);

    cudaFuncSetAttribute(segsum3_kernel,
                         cudaFuncAttributeMaxDynamicSharedMemorySize, SEG3_SMEM_BYTES);

    // 1-2. area histogram (int, deterministic)
    zero_acnt<<<1, 516>>>(acnt);
    hist_kernel<<<dim3(4, 16), 256>>>(mask, acnt);
    // 3. filler (keeps segsum3 on the ncu capture slot)
    zero_buf<<<18, 256>>>(sc + S_GLP, 4608);
    // 4. atomic-free segment sums
    segsum3_kernel<<<dim3(12, 4, 3), 256, SEG3_SMEM_BYTES>>>(hd1, h1, mask,
                                                             sc + S_PART, sc + S_GLP);
    // 5. all_fv (+ area output)
    finalize2<<<512, 256>>>(sc + S_PART, acnt, sc + S_GLP, sc + S_AF, out + O_ARE);
    // 6-7. emb = all_fv @ embed_w, split-K 8 (grid 256)
    launch_gemm(sc + S_AF, 768, 0, embed_w, EE, 0, sc + S_EM, EE, 0,
                512, EE, 768, 0, 1, 8, P);
    // 8. embp + comp fused
    embp_comp_fused<<<4, 256>>>(sc + S_EM, comp_w1, comp_w2, sc + S_CP, out + O_CMP);
    // 9-10. hidden fused (hist + 3 branches), z=4, KS=4 -> grid 512
    gemm64h<<<dim3(4, 8, 16), 256>>>(sc + S_EM, EE, hist_w1, wref_w1,
                                     EE, (long long)EE * EE, P, EE, 512, EE, EE, 4);
    reducek_kernel<<<dim3(512, 4), 256>>>(P, sc + S_HH4, 131072LL, 131072LL, 4, 1);
    // 11. out_cell_type
    gemmN16<<<16, 256, 32 * EE * sizeof(float)>>>(sc + S_HH4, hist_w2, out + O_OCT, EE, 0);
    // 12. rw logits, z=3, KS=8 (grid 192)
    gemm64<<<dim3(1, 8, 24), 256>>>(sc + S_HH4 + 131072, EE, 131072LL,
                                    wref_w2, 64, (long long)EE * 64,
                                    P, 64, 0, 512, 64, EE, 8, 0);
    // 13. fused reduce + softmax
    reduce_softmax64<<<384, 256>>>(P, sc + S_RW);
    // 14. refw = rw @ ref_orig (z=3, KS=1, grid 192)
    launch_gemm(sc + S_RW, 64, (long long)512 * 64, ref_orig, GG, 0,
                out + O_OE0, GG, 262144LL, 512, GG, 64, 0, 3, 1, P);
    // 15-16. kf+vf merged (z=12, KS=2)
    gemm64kv<<<dim3(EE / 64, 512 / 64, 12), 256>>>(out + O_OE0, GG, 262144LL,
                                                   ca_wk, ca_wv, EE, (long long)GG * EE,
                                                   P, EE, 512, EE, GG);
    reducek_kernel<<<dim3(512, 6), 256>>>(P, sc + S_KF, 131072LL, 131072LL, 2, 0);
    // 17. attention
    attn_kernel<<<dim3(4, 8, 3), 256>>>(sc + S_CP, ca_wq, sc + S_KF, sc + S_VF, sc + S_OB);
    // 18. obwo
    obwo_kernel<<<dim3(4, 1, 3), 512>>>(sc + S_OB, ca_wo, sc + S_OW);
    // 19. out_exprs = relu(refw + tile(obwo))
    addrelu_kernel<<<dim3(512, 1, 3), 512>>>(out + O_OE0, sc + S_OW);
    // 20-21. genes_h, split-K 8 (grid 256)
    launch_gemm(out + O_OE0, GG, 0, genes_w1, EE, 0, out + O_GH, EE, 0,
                512, EE, GG, 1, 1, 8, P);
    // 22. out_cell_type_expr
    gemmN16<<<16, 256, 32 * EE * sizeof(float)>>>(out + O_GH, genes_w2, out + O_OCTE, EE, 0);
}